// round 13
// baseline (speedup 1.0000x reference)
#include <cuda_runtime.h>
#include <cstdint>
#include <math.h>

// ---------------- problem constants ----------------
#define BB 8
#define NN 1000
#define EE 4000
#define HH 256

#define MT12 32      // GEMM1/2: M=4000 -> 32 tiles of 128
#define KT12 63      // K=1000  -> 63 tiles of 16
#define MT34 8       // GEMM3/4: M=1000 -> 8 tiles
#define KT34 250     // K=4000  -> 250 tiles

// small-GEMM tiling: M=8000 -> 63 tiles; K=1024 -> 64 kt; K=512 -> 32 kt
#define MTS 63
#define KTF 64
#define KTG 32

#define PA12_SZ (MT12*KT12*4096*BB)
#define PA34_SZ (MT34*KT34*4096*BB)
#define PB_NF_SZ (KT12*2*4096*BB)
#define PB_T_SZ  (KT34*2*4096*BB)
#define PACT_SZ  (MTS*KTF*4096)

#define CSUM_CH 16

// ---------------- scratch (static device globals; no allocation) ----------------
__device__ float g_pA1[PA12_SZ];
__device__ float g_pA2[PA12_SZ];
__device__ float g_pA3[PA34_SZ];
__device__ float g_pA4[PA34_SZ];
__device__ float g_pBnf[PB_NF_SZ];
__device__ float g_pBt1[PB_T_SZ];
__device__ float g_pBt2[PB_T_SZ];
__device__ float g_pAct[PACT_SZ];
__device__ float g_pWf[KTF*2*4096];
__device__ float g_pWz[KTG*2*4096];
__device__ float g_pWr[KTG*2*4096];
__device__ float g_pWt[KTG*2*4096];

__device__ float g_c1[BB*EE];   // row means for pA1 (node2edge rows)
__device__ float g_c2[BB*EE];   // pA2 (edge2node cols)
__device__ float g_c3[BB*NN];   // pA3 (edge2node rows)
__device__ float g_c4[BB*NN];   // pA4 (node2edge cols)
__device__ float g_Snf[BB*256];
__device__ float g_St1[BB*256];
__device__ float g_St2[BB*256];
__device__ float g_Spart[CSUM_CH*BB*256];

__device__ float g_tmp1[BB*EE*HH];
__device__ float g_tmp2[BB*EE*HH];
__device__ float g_bw  [BB*NN*HH];
__device__ float g_fw  [BB*NN*HH];
__device__ float g_agg [BB*NN*HH];
__device__ float g_zg  [BB*NN*HH];
__device__ float g_rg  [BB*NN*HH];
__device__ float g_nf1 [BB*NN*HH];
__device__ float g_WfT [4*HH*HH];
__device__ float g_WzT [2*HH*HH];
__device__ float g_WrT [2*HH*HH];
__device__ float g_WtT [2*HH*HH];

// ---------------- helpers ----------------
__device__ __forceinline__ uint32_t f2tf(float f) {
    uint32_t u; asm("cvt.rna.tf32.f32 %0, %1;" : "=r"(u) : "f"(f)); return u;
}

__device__ __forceinline__ void split2(float x, float& h, float& l) {
    uint32_t hu = f2tf(x);
    h = __uint_as_float(hu);
    float r1 = __fadd_rn(x, -h);
    uint32_t lu = f2tf(r1);
    l = __uint_as_float(lu);
}

__device__ __forceinline__ void mma8(float* d, const uint32_t* a, uint32_t b0, uint32_t b1) {
    asm volatile(
        "mma.sync.aligned.m16n8k8.row.col.f32.tf32.tf32.f32 "
        "{%0,%1,%2,%3},{%4,%5,%6,%7},{%8,%9},{%0,%1,%2,%3};"
        : "+f"(d[0]), "+f"(d[1]), "+f"(d[2]), "+f"(d[3])
        : "r"(a[0]), "r"(a[1]), "r"(a[2]), "r"(a[3]), "r"(b0), "r"(b1));
}

__device__ __forceinline__ void cp_async16(float4* smem_ptr, const float4* gptr) {
    uint32_t s = (uint32_t)__cvta_generic_to_shared(smem_ptr);
    asm volatile("cp.async.cg.shared.global [%0], [%1], 16;" :: "r"(s), "l"(gptr));
}
__device__ __forceinline__ void cp_commit() {
    asm volatile("cp.async.commit_group;");
}
template<int N>
__device__ __forceinline__ void cp_wait() {
    asm volatile("cp.async.wait_group %0;" :: "n"(N));
}

__device__ __forceinline__ int a_frag_off(int mRel, int kRel) {
    int ms = mRel >> 4;
    int ks2 = kRel >> 3;
    int lane = (mRel & 7) * 4 + (kRel & 3);
    int areg = ((kRel >> 2) & 1) * 2 + ((mRel >> 3) & 1);
    return (((ms * 2) + ks2) * 32 + lane) * 4 + areg;
}
__device__ __forceinline__ int b_frag_off(int kRel, int nRel) {
    int ns = nRel >> 3;
    int lane = (nRel & 7) * 4 + (kRel & 3);
    int breg = ((kRel >> 3) & 1) * 2 + ((kRel >> 2) & 1);
    return (ns * 32 + lane) * 4 + breg;
}

// ---------------- mean / colsum kernels ----------------
// contiguous rows: warp per row
__global__ void __launch_bounds__(256)
k_rowmean0(const float* __restrict__ src, float* __restrict__ c,
           int M, int K, int lda, long long sB)
{
    int b = blockIdx.y;
    int row = blockIdx.x * 8 + (threadIdx.x >> 5);
    int lane = threadIdx.x & 31;
    if (row >= M) return;
    const float* S = src + (long long)b * sB + (size_t)row * lda;
    float s = 0.f;
    for (int k = lane; k < K; k += 32) s += S[k];
#pragma unroll
    for (int o = 16; o; o >>= 1) s += __shfl_xor_sync(0xffffffffu, s, o);
    if (lane == 0) c[(size_t)b * M + row] = s * (1.0f / K);
}

// strided rows (transposed source): thread per row
__global__ void __launch_bounds__(256)
k_rowmean1(const float* __restrict__ src, float* __restrict__ c,
           int M, int K, int lda, long long sB)
{
    int b = blockIdx.y;
    int m = blockIdx.x * 256 + threadIdx.x;
    if (m >= M) return;
    const float* S = src + (long long)b * sB + m;
    float s = 0.f;
    for (int k = 0; k < K; k++) s += S[(size_t)k * lda];
    c[(size_t)b * M + m] = s * (1.0f / K);
}

// column sums of B [K,256] row-major, two-stage deterministic
__global__ void __launch_bounds__(256)
k_colsum_part(const float* __restrict__ B, float* __restrict__ part, int K)
{
    int b = blockIdx.y, ch = blockIdx.x, h = threadIdx.x;
    int chunk = (K + CSUM_CH - 1) / CSUM_CH;
    int k0 = ch * chunk, k1 = min(K, k0 + chunk);
    const float* p = B + (long long)b * K * 256 + h;
    float s = 0.f;
    for (int k = k0; k < k1; k++) s += p[(size_t)k * 256];
    part[((size_t)b * CSUM_CH + ch) * 256 + h] = s;
}
__global__ void __launch_bounds__(256)
k_colsum_red(const float* __restrict__ part, float* __restrict__ S)
{
    int b = blockIdx.y, h = threadIdx.x;
    float s = 0.f;
#pragma unroll
    for (int ch = 0; ch < CSUM_CH; ch++) s += part[((size_t)b * CSUM_CH + ch) * 256 + h];
    S[(size_t)b * 256 + h] = s;
}

// ---------------- pack kernels ----------------
// A pack with per-row mean subtraction (centered images)
template<int TRANSA>
__global__ void __launch_bounds__(256)
k_packA(const float* __restrict__ src, const float* __restrict__ cmean, float* __restrict__ dst,
        int M, int K, int lda, long long sSrc, int MT, int KT)
{
    __shared__ float img[4096];
    int kt = blockIdx.x, mt = blockIdx.y, b = blockIdx.z;
    const float* S = src + (long long)b * sSrc;
    const float* cm = cmean + (long long)b * M;
    int m0 = mt * 128, k0 = kt * 16;
    int tid = threadIdx.x;
#pragma unroll
    for (int it = 0; it < 2; it++) {
        int linear = tid + it * 256;
        if (TRANSA == 0) {
            int row = linear >> 2, c4 = (linear & 3) << 2;
            int gm = m0 + row, gk = k0 + c4;
            float cv = (gm < M) ? cm[gm] : 0.f;
#pragma unroll
            for (int j = 0; j < 4; j++) {
                float val = 0.f;
                if (gm < M && gk + j < K)
                    val = __fadd_rn(S[(size_t)gm * lda + gk + j], -cv);
                float h, l;
                split2(val, h, l);
                int off = a_frag_off(row, c4 + j);
                img[off] = h; img[2048 + off] = l;
            }
        } else {
            int kk = linear >> 5, m4 = (linear & 31) << 2;
            int gk = k0 + kk, gm = m0 + m4;
#pragma unroll
            for (int j = 0; j < 4; j++) {
                float val = 0.f;
                if (gk < K && gm + j < M)
                    val = __fadd_rn(S[(size_t)gk * lda + gm + j], -cm[gm + j]);
                float h, l;
                split2(val, h, l);
                int off = a_frag_off(m4 + j, kk);
                img[off] = h; img[2048 + off] = l;
            }
        }
    }
    __syncthreads();
    float4* D = reinterpret_cast<float4*>(dst + (((long long)b * MT + mt) * KT + kt) * 4096);
    const float4* I = reinterpret_cast<const float4*>(img);
#pragma unroll
    for (int i = 0; i < 4; i++) D[tid + i * 256] = I[tid + i * 256];
}

// Fused activation A-pack (small GEMM path, NOT centered — bit-identical to R12)
template<int SRC>
__global__ void __launch_bounds__(256)
k_packA_f(const float* __restrict__ s1, const float* __restrict__ s2, const float* __restrict__ s3,
          float* __restrict__ dst, int KT)
{
    __shared__ float img[4096];
    int kt = blockIdx.x, mt = blockIdx.y;
    int m0 = mt * 128, k0 = kt * 16;
    int tid = threadIdx.x;
#pragma unroll
    for (int it = 0; it < 2; it++) {
        int linear = tid + it * 256;
        int row = linear >> 2, c4 = (linear & 3) << 2;
        int gm = m0 + row;
#pragma unroll
        for (int j = 0; j < 4; j++) {
            int gk = k0 + c4 + j;
            float val = 0.f;
            if (gm < BB * NN) {
                if (SRC == 0) {
                    int feat = gk >> 8, hcol = gk & 255;
                    float f = s1[(size_t)gm * 256 + hcol];
                    float b = s2[(size_t)gm * 256 + hcol];
                    val = (feat == 0) ? f : (feat == 1) ? b : (feat == 2) ? f * b : f - b;
                } else if (SRC == 1) {
                    val = (gk < 256) ? s1[(size_t)gm * 256 + gk]
                                     : s2[(size_t)gm * 256 + (gk - 256)];
                } else {
                    val = (gk < 256) ? s1[(size_t)gm * 256 + gk] * s2[(size_t)gm * 256 + gk]
                                     : s3[(size_t)gm * 256 + (gk - 256)];
                }
            }
            float h, l;
            split2(val, h, l);
            int off = a_frag_off(row, c4 + j);
            img[off] = h; img[2048 + off] = l;
        }
    }
    __syncthreads();
    float4* D = reinterpret_cast<float4*>(dst + ((long long)mt * KT + kt) * 4096);
    const float4* I = reinterpret_cast<const float4*>(img);
#pragma unroll
    for (int i = 0; i < 4; i++) D[tid + i * 256] = I[tid + i * 256];
}

__global__ void __launch_bounds__(256)
k_packB(const float* __restrict__ src, float* __restrict__ dst, int K, int KT)
{
    __shared__ float img[4096];
    int kt = blockIdx.x, nt = blockIdx.y, b = blockIdx.z;
    const float* S = src + (long long)b * K * 256;
    int k0 = kt * 16, n0 = nt * 128;
    int tid = threadIdx.x;
#pragma unroll
    for (int it = 0; it < 2; it++) {
        int linear = tid + it * 256;
        int kr = linear >> 5, n4 = (linear & 31) << 2;
        int gk = k0 + kr;
        float4 v = make_float4(0.f, 0.f, 0.f, 0.f);
        if (gk < K) v = *reinterpret_cast<const float4*>(S + (size_t)gk * 256 + n0 + n4);
        const float* pv = &v.x;
#pragma unroll
        for (int j = 0; j < 4; j++) {
            float h, l;
            split2(pv[j], h, l);
            int off = b_frag_off(kr, n4 + j);
            img[off] = h; img[2048 + off] = l;
        }
    }
    __syncthreads();
    float4* D = reinterpret_cast<float4*>(dst + (((long long)b * KT + kt) * 2 + nt) * 4096);
    const float4* I = reinterpret_cast<const float4*>(img);
#pragma unroll
    for (int i = 0; i < 4; i++) D[tid + i * 256] = I[tid + i * 256];
}

// ---------------- centered big GEMM: 128x128 tile, 2 CTAs/SM, 3-stage ring ----------------
// out = (A-c)B + c*S  — no master accumulator needed (centered partial sums stay small)
#define STAGES_C 3
#define FRAG_SMEM_C (STAGES_C*8192*4)   // 98304 bytes

__global__ void __launch_bounds__(256, 2)
gemm_frag_c(const float* __restrict__ pA, const float* __restrict__ pB, float* __restrict__ C,
            int M, int MT, int KT,
            const float* __restrict__ cmean, const float* __restrict__ Ssum)
{
    extern __shared__ float sm[];
    const int tid = threadIdx.x;
    const int nt = blockIdx.x, mt = blockIdx.y, b = blockIdx.z;
    const float4* Abase = reinterpret_cast<const float4*>(pA) + ((long long)b * MT + mt) * KT * 1024;
    const float4* Bbase = reinterpret_cast<const float4*>(pB) + (long long)b * KT * 2048;

    const int lane = tid & 31, warp = tid >> 5;
    const int wm = warp >> 2, wn = warp & 3;
    const int gid = lane >> 2, tig = lane & 3;

    float acc[64];
#pragma unroll
    for (int i = 0; i < 64; i++) acc[i] = 0.f;

    auto issue = [&](int kt) {
        float4* s = reinterpret_cast<float4*>(sm + (kt % STAGES_C) * 8192);
        const float4* A = Abase + (size_t)kt * 1024;
        const float4* Bt = Bbase + ((size_t)kt * 2 + nt) * 1024;
#pragma unroll
        for (int i = 0; i < 4; i++) cp_async16(s + tid + i * 256, A + tid + i * 256);
#pragma unroll
        for (int i = 0; i < 4; i++) cp_async16(s + 1024 + tid + i * 256, Bt + tid + i * 256);
    };

    auto compute = [&](int stage) {
        const float* sA = sm + stage * 8192;
        const float* sB = sm + stage * 8192 + 4096;
        float4 bh[4], bl[4];
#pragma unroll
        for (int ni = 0; ni < 4; ni++) {
            int ns = wn * 4 + ni;
            bh[ni] = *reinterpret_cast<const float4*>(sB + (ns * 32 + lane) * 4);
            bl[ni] = *reinterpret_cast<const float4*>(sB + 2048 + (ns * 32 + lane) * 4);
        }
#pragma unroll
        for (int ks = 0; ks < 2; ks++) {
#pragma unroll
            for (int mi = 0; mi < 4; mi++) {
                int ms = wm * 4 + mi;
                float4 a4h = *reinterpret_cast<const float4*>(sA + ((ms * 2 + ks) * 32 + lane) * 4);
                float4 a4l = *reinterpret_cast<const float4*>(sA + 2048 + ((ms * 2 + ks) * 32 + lane) * 4);
                uint32_t ah[4] = {__float_as_uint(a4h.x), __float_as_uint(a4h.y),
                                  __float_as_uint(a4h.z), __float_as_uint(a4h.w)};
                uint32_t al[4] = {__float_as_uint(a4l.x), __float_as_uint(a4l.y),
                                  __float_as_uint(a4l.z), __float_as_uint(a4l.w)};
#pragma unroll
                for (int ni = 0; ni < 4; ni++) {
                    float* a4 = &acc[(mi * 4 + ni) * 4];
                    uint32_t bhk0 = (ks == 0) ? __float_as_uint(bh[ni].x) : __float_as_uint(bh[ni].z);
                    uint32_t bhk1 = (ks == 0) ? __float_as_uint(bh[ni].y) : __float_as_uint(bh[ni].w);
                    uint32_t blk0 = (ks == 0) ? __float_as_uint(bl[ni].x) : __float_as_uint(bl[ni].z);
                    uint32_t blk1 = (ks == 0) ? __float_as_uint(bl[ni].y) : __float_as_uint(bl[ni].w);
                    mma8(a4, al, bhk0, bhk1);
                    mma8(a4, ah, blk0, blk1);
                    mma8(a4, ah, bhk0, bhk1);
                }
            }
        }
    };

    issue(0); cp_commit();
    issue(1); cp_commit();
    for (int kt = 0; kt < KT; kt++) {
        cp_wait<1>();
        __syncthreads();
        compute(kt % STAGES_C);
        __syncthreads();
        if (kt + 2 < KT) issue(kt + 2);
        cp_commit();
    }

    float* Cb = C + (long long)b * M * 256;
    const float* cm = cmean + (long long)b * M;
    const float* Sv = Ssum + (long long)b * 256;
#pragma unroll
    for (int mi = 0; mi < 4; mi++) {
#pragma unroll
        for (int ni = 0; ni < 4; ni++) {
            int rB = mt * 128 + wm * 64 + mi * 16 + gid;
            int cB = nt * 128 + wn * 32 + ni * 8 + tig * 2;
#pragma unroll
            for (int rr = 0; rr < 2; rr++) {
                int r = rB + rr * 8;
                if (r < M) {
                    float cv = cm[r];
#pragma unroll
                    for (int c2 = 0; c2 < 2; c2++) {
                        int c = cB + c2;
                        float v = acc[(mi * 4 + ni) * 4 + rr * 2 + c2];
                        Cb[(size_t)r * 256 + c] = __fadd_rn(v, __fmul_rn(cv, Sv[c]));
                    }
                }
            }
        }
    }
}

// ---------------- small GEMM (R12 path, unchanged): 128x64 tile, mst FOLD=1 ----------------
#define STAGES_T 4
#define STAGE_FLOATS 6144
#define FRAG_SMEM (STAGES_T*STAGE_FLOATS*4)   // 98304 bytes

template<int MODE, int FOLD>
__global__ void __launch_bounds__(256, 2)
gemm_frag(const float* __restrict__ pA, const float* __restrict__ pB, float* __restrict__ C,
          int M, int MT, int KT,
          const float* __restrict__ bias,
          const float* __restrict__ aux1, const float* __restrict__ aux2)
{
    extern __shared__ float sm[];
    const int tid = threadIdx.x;
    const int nt4 = blockIdx.x, mt = blockIdx.y, b = blockIdx.z;
    const int nt2 = nt4 >> 1, half = nt4 & 1;
    const float4* Abase = reinterpret_cast<const float4*>(pA) + ((long long)b * MT + mt) * KT * 1024;
    const float4* Bbase = reinterpret_cast<const float4*>(pB) + (long long)b * KT * 2048;

    const int lane = tid & 31, warp = tid >> 5;
    const int wm = warp >> 2, wn = warp & 3;
    const int gid = lane >> 2, tig = lane & 3;

    float acc[32], mst[32];
#pragma unroll
    for (int i = 0; i < 32; i++) { acc[i] = 0.f; mst[i] = 0.f; }

    auto issue = [&](int kt) {
        float4* s = reinterpret_cast<float4*>(sm + (kt % STAGES_T) * STAGE_FLOATS);
        const float4* A = Abase + (size_t)kt * 1024;
        const float4* Bt = Bbase + ((size_t)kt * 2 + nt2) * 1024;
#pragma unroll
        for (int i = 0; i < 4; i++) cp_async16(s + tid + i * 256, A + tid + i * 256);
        cp_async16(s + 1024 + tid, Bt + half * 256 + tid);
        cp_async16(s + 1280 + tid, Bt + 512 + half * 256 + tid);
    };
    auto issueG = [&](int g) {
        int kt0 = g * 2;
        if (kt0 < KT) issue(kt0);
        if (kt0 + 1 < KT) issue(kt0 + 1);
    };

    auto compute = [&](int stage) {
        const float* sA = sm + stage * STAGE_FLOATS;
        const float* sB = sm + stage * STAGE_FLOATS + 4096;
        float4 bh[2], bl[2];
#pragma unroll
        for (int ni = 0; ni < 2; ni++) {
            int nsl = wn * 2 + ni;
            bh[ni] = *reinterpret_cast<const float4*>(sB + (nsl * 32 + lane) * 4);
            bl[ni] = *reinterpret_cast<const float4*>(sB + 1024 + (nsl * 32 + lane) * 4);
        }
#pragma unroll
        for (int ks = 0; ks < 2; ks++) {
#pragma unroll
            for (int mi = 0; mi < 4; mi++) {
                int ms = wm * 4 + mi;
                float4 a4h = *reinterpret_cast<const float4*>(sA + ((ms * 2 + ks) * 32 + lane) * 4);
                float4 a4l = *reinterpret_cast<const float4*>(sA + 2048 + ((ms * 2 + ks) * 32 + lane) * 4);
                uint32_t ah[4] = {__float_as_uint(a4h.x), __float_as_uint(a4h.y),
                                  __float_as_uint(a4h.z), __float_as_uint(a4h.w)};
                uint32_t al[4] = {__float_as_uint(a4l.x), __float_as_uint(a4l.y),
                                  __float_as_uint(a4l.z), __float_as_uint(a4l.w)};
#pragma unroll
                for (int ni = 0; ni < 2; ni++) {
                    float* a4 = &acc[(mi * 2 + ni) * 4];
                    uint32_t bhk0 = (ks == 0) ? __float_as_uint(bh[ni].x) : __float_as_uint(bh[ni].z);
                    uint32_t bhk1 = (ks == 0) ? __float_as_uint(bh[ni].y) : __float_as_uint(bh[ni].w);
                    uint32_t blk0 = (ks == 0) ? __float_as_uint(bl[ni].x) : __float_as_uint(bl[ni].z);
                    uint32_t blk1 = (ks == 0) ? __float_as_uint(bl[ni].y) : __float_as_uint(bl[ni].w);
                    mma8(a4, al, bhk0, bhk1);
                    mma8(a4, ah, blk0, blk1);
                    mma8(a4, ah, bhk0, bhk1);
                }
            }
        }
    };

    auto fold = [&]() {
#pragma unroll
        for (int i = 0; i < 32; i++) { mst[i] = __fadd_rn(mst[i], acc[i]); acc[i] = 0.f; }
    };

    const int NG = (KT + 1) >> 1;
    issueG(0); cp_commit();
    issueG(1); cp_commit();

    for (int g = 0; g < NG; g++) {
        cp_wait<1>();
        __syncthreads();
        int kt = g * 2;
        compute(kt % STAGES_T);
        if (((kt + 1) % FOLD) == 0 || kt == KT - 1) fold();
        if (kt + 1 < KT) {
            compute((kt + 1) % STAGES_T);
            if (((kt + 2) % FOLD) == 0 || kt + 1 == KT - 1) fold();
        }
        __syncthreads();
        issueG(g + 2);
        cp_commit();
    }

    float* Cb = C + (long long)b * M * 256;
#pragma unroll
    for (int mi = 0; mi < 4; mi++) {
#pragma unroll
        for (int ni = 0; ni < 2; ni++) {
            int rB = mt * 128 + wm * 64 + mi * 16 + gid;
            int cB = nt4 * 64 + wn * 16 + ni * 8 + tig * 2;
#pragma unroll
            for (int rr = 0; rr < 2; rr++) {
                int r = rB + rr * 8;
                if (r < M) {
#pragma unroll
                    for (int c2 = 0; c2 < 2; c2++) {
                        int c = cB + c2;
                        float v = mst[(mi * 2 + ni) * 4 + rr * 2 + c2];
                        size_t idx = (size_t)r * 256 + c;
                        if (MODE == 1) {
                            Cb[idx] = 1.f / (1.f + expf(-v));
                        } else if (MODE == 2) {
                            float z = 1.f / (1.f + expf(-(v + bias[c])));
                            Cb[idx] = (1.f - z) * aux1[idx] + z * aux2[idx];
                        } else {
                            float t = tanhf(v);
                            float z = aux1[idx];
                            Cb[idx] = (1.f - z) * aux2[idx] + z * t;
                        }
                    }
                }
            }
        }
    }
}

// ---------------- fused weight transpose ----------------
__global__ void k_transW(const float* __restrict__ Wf, const float* __restrict__ Wz,
                         const float* __restrict__ Wr, const float* __restrict__ Wt,
                         float* __restrict__ WfT, float* __restrict__ WzT,
                         float* __restrict__ WrT, float* __restrict__ WtT)
{
    __shared__ float t[32][33];
    int x = threadIdx.x, y = threadIdx.y;
    const float* srcs[4] = {Wf, Wz, Wr, Wt};
    float* dsts[4] = {WfT, WzT, WrT, WtT};
    const int Cs[4] = {1024, 512, 512, 512};
#pragma unroll
    for (int w = 0; w < 4; w++) {
        int C = Cs[w];
        const int R = 256;
        if (blockIdx.x * 32 >= C) continue;
        int bx = blockIdx.x * 32, by = blockIdx.y * 32;
        __syncthreads();
#pragma unroll
        for (int j = 0; j < 32; j += 8) {
            int r = by + y + j, c = bx + x;
            t[y + j][x] = srcs[w][(size_t)r * C + c];
        }
        __syncthreads();
#pragma unroll
        for (int j = 0; j < 32; j += 8) {
            int r = bx + y + j, c = by + x;
            dsts[w][(size_t)r * R + c] = t[x][y + j];
        }
    }
}

// ---------------- host side ----------------
static void run_frag_c(const float* pA, const float* pB, float* C, int M, int MT, int KT,
                       const float* cmean, const float* Ssum)
{
    cudaFuncSetAttribute(gemm_frag_c, cudaFuncAttributeMaxDynamicSharedMemorySize, FRAG_SMEM_C);
    dim3 grid(2, MT, BB);
    gemm_frag_c<<<grid, 256, FRAG_SMEM_C>>>(pA, pB, C, M, MT, KT, cmean, Ssum);
}

template<int MODE, int FOLD>
static void run_frag(const float* pA, const float* pB, float* C, int M, int MT, int KT, int batch,
                     const float* bias, const float* a1, const float* a2)
{
    cudaFuncSetAttribute(gemm_frag<MODE, FOLD>, cudaFuncAttributeMaxDynamicSharedMemorySize, FRAG_SMEM);
    dim3 grid(4, MT, batch);
    gemm_frag<MODE, FOLD><<<grid, 256, FRAG_SMEM>>>(pA, pB, C, M, MT, KT, bias, a1, a2);
}

extern "C" void kernel_launch(void* const* d_in, const int* in_sizes, int n_in,
                              void* d_out, int out_size)
{
    const float* node_feature = (const float*)d_in[0];
    const float* node2edge    = (const float*)d_in[1];
    const float* edge2node    = (const float*)d_in[2];
    const float* Wz = (const float*)d_in[3];
    const float* Wr = (const float*)d_in[4];
    const float* Wt = (const float*)d_in[5];
    const float* Wf = (const float*)d_in[6];
    const float* bf = (const float*)d_in[7];
    float* out = (float*)d_out;

    float *pA1, *pA2, *pA3, *pA4, *pBnf, *pBt1, *pBt2, *pAct, *pWf, *pWz, *pWr, *pWt;
    float *c1, *c2, *c3, *c4, *Snf, *St1, *St2, *Spart;
    float *tmp1, *tmp2, *bwP, *fwP, *agg, *zg, *rg, *nf1;
    float *WfT, *WzT, *WrT, *WtT;
    cudaGetSymbolAddress((void**)&pA1, g_pA1);
    cudaGetSymbolAddress((void**)&pA2, g_pA2);
    cudaGetSymbolAddress((void**)&pA3, g_pA3);
    cudaGetSymbolAddress((void**)&pA4, g_pA4);
    cudaGetSymbolAddress((void**)&pBnf, g_pBnf);
    cudaGetSymbolAddress((void**)&pBt1, g_pBt1);
    cudaGetSymbolAddress((void**)&pBt2, g_pBt2);
    cudaGetSymbolAddress((void**)&pAct, g_pAct);
    cudaGetSymbolAddress((void**)&pWf, g_pWf);
    cudaGetSymbolAddress((void**)&pWz, g_pWz);
    cudaGetSymbolAddress((void**)&pWr, g_pWr);
    cudaGetSymbolAddress((void**)&pWt, g_pWt);
    cudaGetSymbolAddress((void**)&c1, g_c1);
    cudaGetSymbolAddress((void**)&c2, g_c2);
    cudaGetSymbolAddress((void**)&c3, g_c3);
    cudaGetSymbolAddress((void**)&c4, g_c4);
    cudaGetSymbolAddress((void**)&Snf, g_Snf);
    cudaGetSymbolAddress((void**)&St1, g_St1);
    cudaGetSymbolAddress((void**)&St2, g_St2);
    cudaGetSymbolAddress((void**)&Spart, g_Spart);
    cudaGetSymbolAddress((void**)&tmp1, g_tmp1);
    cudaGetSymbolAddress((void**)&tmp2, g_tmp2);
    cudaGetSymbolAddress((void**)&bwP,  g_bw);
    cudaGetSymbolAddress((void**)&fwP,  g_fw);
    cudaGetSymbolAddress((void**)&agg,  g_agg);
    cudaGetSymbolAddress((void**)&zg,   g_zg);
    cudaGetSymbolAddress((void**)&rg,   g_rg);
    cudaGetSymbolAddress((void**)&nf1,  g_nf1);
    cudaGetSymbolAddress((void**)&WfT,  g_WfT);
    cudaGetSymbolAddress((void**)&WzT,  g_WzT);
    cudaGetSymbolAddress((void**)&WrT,  g_WrT);
    cudaGetSymbolAddress((void**)&WtT,  g_WtT);

    // weights: one fused transpose launch, then B-images
    k_transW<<<dim3(32, 8), dim3(32, 8)>>>(Wf, Wz, Wr, Wt, WfT, WzT, WrT, WtT);
    k_packB<<<dim3(KTF, 2, 1), 256>>>(WfT, pWf, 4 * HH, KTF);
    k_packB<<<dim3(KTG, 2, 1), 256>>>(WzT, pWz, 2 * HH, KTG);
    k_packB<<<dim3(KTG, 2, 1), 256>>>(WrT, pWr, 2 * HH, KTG);
    k_packB<<<dim3(KTG, 2, 1), 256>>>(WtT, pWt, 2 * HH, KTG);

    const long long sPQ = (long long)EE * NN;
    const int MR = BB * NN;   // 8000

    // row means for the 4 A operands
    k_rowmean0<<<dim3((EE + 7) / 8, BB), 256>>>(node2edge, c1, EE, NN, NN, sPQ);
    k_rowmean1<<<dim3((EE + 255) / 256, BB), 256>>>(edge2node, c2, EE, NN, EE, sPQ);
    k_rowmean0<<<dim3((NN + 7) / 8, BB), 256>>>(edge2node, c3, NN, EE, EE, sPQ);
    k_rowmean1<<<dim3((NN + 255) / 256, BB), 256>>>(node2edge, c4, NN, EE, NN, sPQ);

    // pack CENTERED adjacency fragment images (reused both hops)
    k_packA<0><<<dim3(KT12, MT12, BB), 256>>>(node2edge, c1, pA1, EE, NN, NN, sPQ, MT12, KT12);
    k_packA<1><<<dim3(KT12, MT12, BB), 256>>>(edge2node, c2, pA2, EE, NN, EE, sPQ, MT12, KT12);
    k_packA<0><<<dim3(KT34, MT34, BB), 256>>>(edge2node, c3, pA3, NN, EE, EE, sPQ, MT34, KT34);
    k_packA<1><<<dim3(KT34, MT34, BB), 256>>>(node2edge, c4, pA4, NN, EE, NN, sPQ, MT34, KT34);

    const float* nfIn = node_feature;
    for (int hop = 0; hop < 2; hop++) {
        float* nfOut = (hop == 1) ? out : nf1;

        // pack nf as B image + column sums
        k_packB<<<dim3(KT12, 2, BB), 256>>>(nfIn, pBnf, NN, KT12);
        k_colsum_part<<<dim3(CSUM_CH, BB), 256>>>(nfIn, Spart, NN);
        k_colsum_red<<<dim3(1, BB), 256>>>(Spart, Snf);

        // tmp1 = node2edge @ nf ; tmp2 = edge2node^T @ nf  (centered + correction)
        run_frag_c(pA1, pBnf, tmp1, EE, MT12, KT12, c1, Snf);
        run_frag_c(pA2, pBnf, tmp2, EE, MT12, KT12, c2, Snf);

        // pack tmp images + their column sums
        k_packB<<<dim3(KT34, 2, BB), 256>>>(tmp1, pBt1, EE, KT34);
        k_packB<<<dim3(KT34, 2, BB), 256>>>(tmp2, pBt2, EE, KT34);
        k_colsum_part<<<dim3(CSUM_CH, BB), 256>>>(tmp1, Spart, EE);
        k_colsum_red<<<dim3(1, BB), 256>>>(Spart, St1);
        k_colsum_part<<<dim3(CSUM_CH, BB), 256>>>(tmp2, Spart, EE);
        k_colsum_red<<<dim3(1, BB), 256>>>(Spart, St2);

        // bw = edge2node @ tmp1 ; fw = node2edge^T @ tmp2
        run_frag_c(pA3, pBt1, bwP, NN, MT34, KT34, c3, St1);
        run_frag_c(pA4, pBt2, fwP, NN, MT34, KT34, c4, St2);

        // gated fusion (small path unchanged)
        k_packA_f<0><<<dim3(KTF, MTS), 256>>>(fwP, bwP, nullptr, pAct, KTF);
        run_frag<2, 1>(pAct, pWf, agg, MR, MTS, KTF, 1, bf, fwP, bwP);

        // GRU step
        k_packA_f<1><<<dim3(KTG, MTS), 256>>>(nfIn, agg, nullptr, pAct, KTG);
        run_frag<1, 1>(pAct, pWz, zg, MR, MTS, KTG, 1, nullptr, nullptr, nullptr);
        run_frag<1, 1>(pAct, pWr, rg, MR, MTS, KTG, 1, nullptr, nullptr, nullptr);
        k_packA_f<2><<<dim3(KTG, MTS), 256>>>(rg, nfIn, agg, pAct, KTG);
        run_frag<3, 1>(pAct, pWt, nfOut, MR, MTS, KTG, 1, nullptr, zg, nfIn);

        nfIn = nfOut;
    }
}

// round 14
// speedup vs baseline: 1.0243x; 1.0243x over previous
#include <cuda_runtime.h>
#include <cstdint>
#include <math.h>

// ---------------- problem constants ----------------
#define BB 8
#define NN 1000
#define EE 4000
#define HH 256

#define MT12 32
#define KT12 63
#define MT34 8
#define KT34 250

#define MTS 63
#define KTF 64
#define KTG 32

#define PA12_SZ (MT12*KT12*4096*BB)
#define PA34_SZ (MT34*KT34*4096*BB)
#define PB_NF_SZ (KT12*2*4096*BB)
#define PB_T_SZ  (KT34*2*4096*BB)
#define PACT_SZ  (MTS*KTF*4096)

#define CSUM_CH 16

// ---------------- scratch ----------------
__device__ float g_pA1[PA12_SZ];
__device__ float g_pA2[PA12_SZ];
__device__ float g_pA3[PA34_SZ];
__device__ float g_pA4[PA34_SZ];
__device__ float g_pBnf[PB_NF_SZ];
__device__ float g_pBt1[PB_T_SZ];
__device__ float g_pBt2[PB_T_SZ];
__device__ float g_pAct[PACT_SZ];
__device__ float g_pWf[KTF*2*4096];
__device__ float g_pWz[KTG*2*4096];
__device__ float g_pWr[KTG*2*4096];
__device__ float g_pWt[KTG*2*4096];

__device__ float g_c1[BB*EE];
__device__ float g_c2[BB*EE];
__device__ float g_c3[BB*NN];
__device__ float g_c4[BB*NN];
__device__ float g_Snf[BB*256];
__device__ float g_St1[BB*256];
__device__ float g_St2[BB*256];
__device__ float g_Spart[CSUM_CH*BB*256];

__device__ float g_tmp1[BB*EE*HH];
__device__ float g_tmp2[BB*EE*HH];
__device__ float g_bw  [BB*NN*HH];
__device__ float g_fw  [BB*NN*HH];
__device__ float g_agg [BB*NN*HH];
__device__ float g_zg  [BB*NN*HH];
__device__ float g_rg  [BB*NN*HH];
__device__ float g_nf1 [BB*NN*HH];
__device__ float g_WfT [4*HH*HH];
__device__ float g_WzT [2*HH*HH];
__device__ float g_WrT [2*HH*HH];
__device__ float g_WtT [2*HH*HH];

// ---------------- helpers ----------------
__device__ __forceinline__ uint32_t f2tf(float f) {
    uint32_t u; asm("cvt.rna.tf32.f32 %0, %1;" : "=r"(u) : "f"(f)); return u;
}

__device__ __forceinline__ void split2(float x, float& h, float& l) {
    uint32_t hu = f2tf(x);
    h = __uint_as_float(hu);
    float r1 = __fadd_rn(x, -h);
    uint32_t lu = f2tf(r1);
    l = __uint_as_float(lu);
}

__device__ __forceinline__ void mma8(float* d, const uint32_t* a, uint32_t b0, uint32_t b1) {
    asm volatile(
        "mma.sync.aligned.m16n8k8.row.col.f32.tf32.tf32.f32 "
        "{%0,%1,%2,%3},{%4,%5,%6,%7},{%8,%9},{%0,%1,%2,%3};"
        : "+f"(d[0]), "+f"(d[1]), "+f"(d[2]), "+f"(d[3])
        : "r"(a[0]), "r"(a[1]), "r"(a[2]), "r"(a[3]), "r"(b0), "r"(b1));
}

__device__ __forceinline__ void cp_async16(float4* smem_ptr, const float4* gptr) {
    uint32_t s = (uint32_t)__cvta_generic_to_shared(smem_ptr);
    asm volatile("cp.async.cg.shared.global [%0], [%1], 16;" :: "r"(s), "l"(gptr));
}
__device__ __forceinline__ void cp_commit() {
    asm volatile("cp.async.commit_group;");
}
template<int N>
__device__ __forceinline__ void cp_wait() {
    asm volatile("cp.async.wait_group %0;" :: "n"(N));
}

__device__ __forceinline__ int a_frag_off(int mRel, int kRel) {
    int ms = mRel >> 4;
    int ks2 = kRel >> 3;
    int lane = (mRel & 7) * 4 + (kRel & 3);
    int areg = ((kRel >> 2) & 1) * 2 + ((mRel >> 3) & 1);
    return (((ms * 2) + ks2) * 32 + lane) * 4 + areg;
}
__device__ __forceinline__ int b_frag_off(int kRel, int nRel) {
    int ns = nRel >> 3;
    int lane = (nRel & 7) * 4 + (kRel & 3);
    int breg = ((kRel >> 3) & 1) * 2 + ((kRel >> 2) & 1);
    return (ns * 32 + lane) * 4 + breg;
}

// ---------------- mean / colsum kernels ----------------
__global__ void __launch_bounds__(256)
k_rowmean0(const float* __restrict__ src, float* __restrict__ c,
           int M, int K, int lda, long long sB)
{
    int b = blockIdx.y;
    int row = blockIdx.x * 8 + (threadIdx.x >> 5);
    int lane = threadIdx.x & 31;
    if (row >= M) return;
    const float* S = src + (long long)b * sB + (size_t)row * lda;
    float s = 0.f;
    for (int k = lane; k < K; k += 32) s += S[k];
#pragma unroll
    for (int o = 16; o; o >>= 1) s += __shfl_xor_sync(0xffffffffu, s, o);
    if (lane == 0) c[(size_t)b * M + row] = s * (1.0f / K);
}

__global__ void __launch_bounds__(256)
k_rowmean1(const float* __restrict__ src, float* __restrict__ c,
           int M, int K, int lda, long long sB)
{
    int b = blockIdx.y;
    int m = blockIdx.x * 256 + threadIdx.x;
    if (m >= M) return;
    const float* S = src + (long long)b * sB + m;
    float s = 0.f;
    for (int k = 0; k < K; k++) s += S[(size_t)k * lda];
    c[(size_t)b * M + m] = s * (1.0f / K);
}

__global__ void __launch_bounds__(256)
k_colsum_part(const float* __restrict__ B, float* __restrict__ part, int K)
{
    int b = blockIdx.y, ch = blockIdx.x, h = threadIdx.x;
    int chunk = (K + CSUM_CH - 1) / CSUM_CH;
    int k0 = ch * chunk, k1 = min(K, k0 + chunk);
    const float* p = B + (long long)b * K * 256 + h;
    float s = 0.f;
    for (int k = k0; k < k1; k++) s += p[(size_t)k * 256];
    part[((size_t)b * CSUM_CH + ch) * 256 + h] = s;
}
__global__ void __launch_bounds__(256)
k_colsum_red(const float* __restrict__ part, float* __restrict__ S)
{
    int b = blockIdx.y, h = threadIdx.x;
    float s = 0.f;
#pragma unroll
    for (int ch = 0; ch < CSUM_CH; ch++) s += part[((size_t)b * CSUM_CH + ch) * 256 + h];
    S[(size_t)b * 256 + h] = s;
}

// ---------------- pack kernels ----------------
template<int TRANSA>
__global__ void __launch_bounds__(256)
k_packA(const float* __restrict__ src, const float* __restrict__ cmean, float* __restrict__ dst,
        int M, int K, int lda, long long sSrc, int MT, int KT)
{
    __shared__ float img[4096];
    int kt = blockIdx.x, mt = blockIdx.y, b = blockIdx.z;
    const float* S = src + (long long)b * sSrc;
    const float* cm = cmean + (long long)b * M;
    int m0 = mt * 128, k0 = kt * 16;
    int tid = threadIdx.x;
#pragma unroll
    for (int it = 0; it < 2; it++) {
        int linear = tid + it * 256;
        if (TRANSA == 0) {
            int row = linear >> 2, c4 = (linear & 3) << 2;
            int gm = m0 + row, gk = k0 + c4;
            float cv = (gm < M) ? cm[gm] : 0.f;
#pragma unroll
            for (int j = 0; j < 4; j++) {
                float val = 0.f;
                if (gm < M && gk + j < K)
                    val = __fadd_rn(S[(size_t)gm * lda + gk + j], -cv);
                float h, l;
                split2(val, h, l);
                int off = a_frag_off(row, c4 + j);
                img[off] = h; img[2048 + off] = l;
            }
        } else {
            int kk = linear >> 5, m4 = (linear & 31) << 2;
            int gk = k0 + kk, gm = m0 + m4;
#pragma unroll
            for (int j = 0; j < 4; j++) {
                float val = 0.f;
                if (gk < K && gm + j < M)
                    val = __fadd_rn(S[(size_t)gk * lda + gm + j], -cm[gm + j]);
                float h, l;
                split2(val, h, l);
                int off = a_frag_off(m4 + j, kk);
                img[off] = h; img[2048 + off] = l;
            }
        }
    }
    __syncthreads();
    float4* D = reinterpret_cast<float4*>(dst + (((long long)b * MT + mt) * KT + kt) * 4096);
    const float4* I = reinterpret_cast<const float4*>(img);
#pragma unroll
    for (int i = 0; i < 4; i++) D[tid + i * 256] = I[tid + i * 256];
}

template<int SRC>
__global__ void __launch_bounds__(256)
k_packA_f(const float* __restrict__ s1, const float* __restrict__ s2, const float* __restrict__ s3,
          float* __restrict__ dst, int KT)
{
    __shared__ float img[4096];
    int kt = blockIdx.x, mt = blockIdx.y;
    int m0 = mt * 128, k0 = kt * 16;
    int tid = threadIdx.x;
#pragma unroll
    for (int it = 0; it < 2; it++) {
        int linear = tid + it * 256;
        int row = linear >> 2, c4 = (linear & 3) << 2;
        int gm = m0 + row;
#pragma unroll
        for (int j = 0; j < 4; j++) {
            int gk = k0 + c4 + j;
            float val = 0.f;
            if (gm < BB * NN) {
                if (SRC == 0) {
                    int feat = gk >> 8, hcol = gk & 255;
                    float f = s1[(size_t)gm * 256 + hcol];
                    float b = s2[(size_t)gm * 256 + hcol];
                    val = (feat == 0) ? f : (feat == 1) ? b : (feat == 2) ? f * b : f - b;
                } else if (SRC == 1) {
                    val = (gk < 256) ? s1[(size_t)gm * 256 + gk]
                                     : s2[(size_t)gm * 256 + (gk - 256)];
                } else {
                    val = (gk < 256) ? s1[(size_t)gm * 256 + gk] * s2[(size_t)gm * 256 + gk]
                                     : s3[(size_t)gm * 256 + (gk - 256)];
                }
            }
            float h, l;
            split2(val, h, l);
            int off = a_frag_off(row, c4 + j);
            img[off] = h; img[2048 + off] = l;
        }
    }
    __syncthreads();
    float4* D = reinterpret_cast<float4*>(dst + ((long long)mt * KT + kt) * 4096);
    const float4* I = reinterpret_cast<const float4*>(img);
#pragma unroll
    for (int i = 0; i < 4; i++) D[tid + i * 256] = I[tid + i * 256];
}

__global__ void __launch_bounds__(256)
k_packB(const float* __restrict__ src, float* __restrict__ dst, int K, int KT)
{
    __shared__ float img[4096];
    int kt = blockIdx.x, nt = blockIdx.y, b = blockIdx.z;
    const float* S = src + (long long)b * K * 256;
    int k0 = kt * 16, n0 = nt * 128;
    int tid = threadIdx.x;
#pragma unroll
    for (int it = 0; it < 2; it++) {
        int linear = tid + it * 256;
        int kr = linear >> 5, n4 = (linear & 31) << 2;
        int gk = k0 + kr;
        float4 v = make_float4(0.f, 0.f, 0.f, 0.f);
        if (gk < K) v = *reinterpret_cast<const float4*>(S + (size_t)gk * 256 + n0 + n4);
        const float* pv = &v.x;
#pragma unroll
        for (int j = 0; j < 4; j++) {
            float h, l;
            split2(pv[j], h, l);
            int off = b_frag_off(kr, n4 + j);
            img[off] = h; img[2048 + off] = l;
        }
    }
    __syncthreads();
    float4* D = reinterpret_cast<float4*>(dst + (((long long)b * KT + kt) * 2 + nt) * 4096);
    const float4* I = reinterpret_cast<const float4*>(img);
#pragma unroll
    for (int i = 0; i < 4; i++) D[tid + i * 256] = I[tid + i * 256];
}

// ---------------- centered big GEMM, 128x128 tile (for GEMM1/2, large grids) ----------------
// out = (A-c)B + c*S ; single __syncthreads per k-tile (issue target stage was
// finished by all warps before the top-of-loop barrier)
#define STAGES_C 3
#define FRAG_SMEM_C (STAGES_C*8192*4)   // 98304 bytes

__global__ void __launch_bounds__(256, 2)
gemm_frag_c128(const float* __restrict__ pA, const float* __restrict__ pB, float* __restrict__ C,
               int M, int MT, int KT,
               const float* __restrict__ cmean, const float* __restrict__ Ssum)
{
    extern __shared__ float sm[];
    const int tid = threadIdx.x;
    const int nt = blockIdx.x, mt = blockIdx.y, b = blockIdx.z;
    const float4* Abase = reinterpret_cast<const float4*>(pA) + ((long long)b * MT + mt) * KT * 1024;
    const float4* Bbase = reinterpret_cast<const float4*>(pB) + (long long)b * KT * 2048;

    const int lane = tid & 31, warp = tid >> 5;
    const int wm = warp >> 2, wn = warp & 3;
    const int gid = lane >> 2, tig = lane & 3;

    float acc[64];
#pragma unroll
    for (int i = 0; i < 64; i++) acc[i] = 0.f;

    auto issue = [&](int kt) {
        float4* s = reinterpret_cast<float4*>(sm + (kt % STAGES_C) * 8192);
        const float4* A = Abase + (size_t)kt * 1024;
        const float4* Bt = Bbase + ((size_t)kt * 2 + nt) * 1024;
#pragma unroll
        for (int i = 0; i < 4; i++) cp_async16(s + tid + i * 256, A + tid + i * 256);
#pragma unroll
        for (int i = 0; i < 4; i++) cp_async16(s + 1024 + tid + i * 256, Bt + tid + i * 256);
    };

    auto compute = [&](int stage) {
        const float* sA = sm + stage * 8192;
        const float* sB = sm + stage * 8192 + 4096;
        float4 bh[4], bl[4];
#pragma unroll
        for (int ni = 0; ni < 4; ni++) {
            int ns = wn * 4 + ni;
            bh[ni] = *reinterpret_cast<const float4*>(sB + (ns * 32 + lane) * 4);
            bl[ni] = *reinterpret_cast<const float4*>(sB + 2048 + (ns * 32 + lane) * 4);
        }
#pragma unroll
        for (int ks = 0; ks < 2; ks++) {
#pragma unroll
            for (int mi = 0; mi < 4; mi++) {
                int ms = wm * 4 + mi;
                float4 a4h = *reinterpret_cast<const float4*>(sA + ((ms * 2 + ks) * 32 + lane) * 4);
                float4 a4l = *reinterpret_cast<const float4*>(sA + 2048 + ((ms * 2 + ks) * 32 + lane) * 4);
                uint32_t ah[4] = {__float_as_uint(a4h.x), __float_as_uint(a4h.y),
                                  __float_as_uint(a4h.z), __float_as_uint(a4h.w)};
                uint32_t al[4] = {__float_as_uint(a4l.x), __float_as_uint(a4l.y),
                                  __float_as_uint(a4l.z), __float_as_uint(a4l.w)};
#pragma unroll
                for (int ni = 0; ni < 4; ni++) {
                    float* a4 = &acc[(mi * 4 + ni) * 4];
                    uint32_t bhk0 = (ks == 0) ? __float_as_uint(bh[ni].x) : __float_as_uint(bh[ni].z);
                    uint32_t bhk1 = (ks == 0) ? __float_as_uint(bh[ni].y) : __float_as_uint(bh[ni].w);
                    uint32_t blk0 = (ks == 0) ? __float_as_uint(bl[ni].x) : __float_as_uint(bl[ni].z);
                    uint32_t blk1 = (ks == 0) ? __float_as_uint(bl[ni].y) : __float_as_uint(bl[ni].w);
                    mma8(a4, al, bhk0, bhk1);
                    mma8(a4, ah, blk0, blk1);
                    mma8(a4, ah, bhk0, bhk1);
                }
            }
        }
    };

    issue(0); cp_commit();
    issue(1); cp_commit();
    for (int kt = 0; kt < KT; kt++) {
        cp_wait<1>();
        __syncthreads();
        compute(kt % STAGES_C);
        if (kt + 2 < KT) issue(kt + 2);   // writes stage (kt-1)%3: safe past top barrier
        cp_commit();
    }

    float* Cb = C + (long long)b * M * 256;
    const float* cm = cmean + (long long)b * M;
    const float* Sv = Ssum + (long long)b * 256;
#pragma unroll
    for (int mi = 0; mi < 4; mi++) {
#pragma unroll
        for (int ni = 0; ni < 4; ni++) {
            int rB = mt * 128 + wm * 64 + mi * 16 + gid;
            int cB = nt * 128 + wn * 32 + ni * 8 + tig * 2;
#pragma unroll
            for (int rr = 0; rr < 2; rr++) {
                int r = rB + rr * 8;
                if (r < M) {
                    float cv = cm[r];
#pragma unroll
                    for (int c2 = 0; c2 < 2; c2++) {
                        int c = cB + c2;
                        float v = acc[(mi * 4 + ni) * 4 + rr * 2 + c2];
                        Cb[(size_t)r * 256 + c] = __fadd_rn(v, __fmul_rn(cv, Sv[c]));
                    }
                }
            }
        }
    }
}

// ---------------- centered big GEMM, 128x64 tile (for GEMM3/4, small grids) ----------------
// R12 granule pipeline minus mst/folds plus rank-1 epilogue correction.
#define STAGES_T 4
#define STAGE_FLOATS 6144
#define FRAG_SMEM_T (STAGES_T*STAGE_FLOATS*4)   // 98304 bytes

__global__ void __launch_bounds__(256, 2)
gemm_frag_c64(const float* __restrict__ pA, const float* __restrict__ pB, float* __restrict__ C,
              int M, int MT, int KT,
              const float* __restrict__ cmean, const float* __restrict__ Ssum)
{
    extern __shared__ float sm[];
    const int tid = threadIdx.x;
    const int nt4 = blockIdx.x, mt = blockIdx.y, b = blockIdx.z;
    const int nt2 = nt4 >> 1, half = nt4 & 1;
    const float4* Abase = reinterpret_cast<const float4*>(pA) + ((long long)b * MT + mt) * KT * 1024;
    const float4* Bbase = reinterpret_cast<const float4*>(pB) + (long long)b * KT * 2048;

    const int lane = tid & 31, warp = tid >> 5;
    const int wm = warp >> 2, wn = warp & 3;
    const int gid = lane >> 2, tig = lane & 3;

    float acc[32];
#pragma unroll
    for (int i = 0; i < 32; i++) acc[i] = 0.f;

    auto issue = [&](int kt) {
        float4* s = reinterpret_cast<float4*>(sm + (kt % STAGES_T) * STAGE_FLOATS);
        const float4* A = Abase + (size_t)kt * 1024;
        const float4* Bt = Bbase + ((size_t)kt * 2 + nt2) * 1024;
#pragma unroll
        for (int i = 0; i < 4; i++) cp_async16(s + tid + i * 256, A + tid + i * 256);
        cp_async16(s + 1024 + tid, Bt + half * 256 + tid);
        cp_async16(s + 1280 + tid, Bt + 512 + half * 256 + tid);
    };
    auto issueG = [&](int g) {
        int kt0 = g * 2;
        if (kt0 < KT) issue(kt0);
        if (kt0 + 1 < KT) issue(kt0 + 1);
    };

    auto compute = [&](int stage) {
        const float* sA = sm + stage * STAGE_FLOATS;
        const float* sB = sm + stage * STAGE_FLOATS + 4096;
        float4 bh[2], bl[2];
#pragma unroll
        for (int ni = 0; ni < 2; ni++) {
            int nsl = wn * 2 + ni;
            bh[ni] = *reinterpret_cast<const float4*>(sB + (nsl * 32 + lane) * 4);
            bl[ni] = *reinterpret_cast<const float4*>(sB + 1024 + (nsl * 32 + lane) * 4);
        }
#pragma unroll
        for (int ks = 0; ks < 2; ks++) {
#pragma unroll
            for (int mi = 0; mi < 4; mi++) {
                int ms = wm * 4 + mi;
                float4 a4h = *reinterpret_cast<const float4*>(sA + ((ms * 2 + ks) * 32 + lane) * 4);
                float4 a4l = *reinterpret_cast<const float4*>(sA + 2048 + ((ms * 2 + ks) * 32 + lane) * 4);
                uint32_t ah[4] = {__float_as_uint(a4h.x), __float_as_uint(a4h.y),
                                  __float_as_uint(a4h.z), __float_as_uint(a4h.w)};
                uint32_t al[4] = {__float_as_uint(a4l.x), __float_as_uint(a4l.y),
                                  __float_as_uint(a4l.z), __float_as_uint(a4l.w)};
#pragma unroll
                for (int ni = 0; ni < 2; ni++) {
                    float* a4 = &acc[(mi * 2 + ni) * 4];
                    uint32_t bhk0 = (ks == 0) ? __float_as_uint(bh[ni].x) : __float_as_uint(bh[ni].z);
                    uint32_t bhk1 = (ks == 0) ? __float_as_uint(bh[ni].y) : __float_as_uint(bh[ni].w);
                    uint32_t blk0 = (ks == 0) ? __float_as_uint(bl[ni].x) : __float_as_uint(bl[ni].z);
                    uint32_t blk1 = (ks == 0) ? __float_as_uint(bl[ni].y) : __float_as_uint(bl[ni].w);
                    mma8(a4, al, bhk0, bhk1);
                    mma8(a4, ah, blk0, blk1);
                    mma8(a4, ah, bhk0, bhk1);
                }
            }
        }
    };

    const int NG = (KT + 1) >> 1;
    issueG(0); cp_commit();
    issueG(1); cp_commit();

    for (int g = 0; g < NG; g++) {
        cp_wait<1>();
        __syncthreads();
        int kt = g * 2;
        compute(kt % STAGES_T);
        if (kt + 1 < KT) compute((kt + 1) % STAGES_T);
        __syncthreads();
        issueG(g + 2);
        cp_commit();
    }

    float* Cb = C + (long long)b * M * 256;
    const float* cm = cmean + (long long)b * M;
    const float* Sv = Ssum + (long long)b * 256;
#pragma unroll
    for (int mi = 0; mi < 4; mi++) {
#pragma unroll
        for (int ni = 0; ni < 2; ni++) {
            int rB = mt * 128 + wm * 64 + mi * 16 + gid;
            int cB = nt4 * 64 + wn * 16 + ni * 8 + tig * 2;
#pragma unroll
            for (int rr = 0; rr < 2; rr++) {
                int r = rB + rr * 8;
                if (r < M) {
                    float cv = cm[r];
#pragma unroll
                    for (int c2 = 0; c2 < 2; c2++) {
                        int c = cB + c2;
                        float v = acc[(mi * 2 + ni) * 4 + rr * 2 + c2];
                        Cb[(size_t)r * 256 + c] = __fadd_rn(v, __fmul_rn(cv, Sv[c]));
                    }
                }
            }
        }
    }
}

// ---------------- small GEMM (R12 path, unchanged): 128x64 tile, mst FOLD=1 ----------------
template<int MODE, int FOLD>
__global__ void __launch_bounds__(256, 2)
gemm_frag(const float* __restrict__ pA, const float* __restrict__ pB, float* __restrict__ C,
          int M, int MT, int KT,
          const float* __restrict__ bias,
          const float* __restrict__ aux1, const float* __restrict__ aux2)
{
    extern __shared__ float sm[];
    const int tid = threadIdx.x;
    const int nt4 = blockIdx.x, mt = blockIdx.y, b = blockIdx.z;
    const int nt2 = nt4 >> 1, half = nt4 & 1;
    const float4* Abase = reinterpret_cast<const float4*>(pA) + ((long long)b * MT + mt) * KT * 1024;
    const float4* Bbase = reinterpret_cast<const float4*>(pB) + (long long)b * KT * 2048;

    const int lane = tid & 31, warp = tid >> 5;
    const int wm = warp >> 2, wn = warp & 3;
    const int gid = lane >> 2, tig = lane & 3;

    float acc[32], mst[32];
#pragma unroll
    for (int i = 0; i < 32; i++) { acc[i] = 0.f; mst[i] = 0.f; }

    auto issue = [&](int kt) {
        float4* s = reinterpret_cast<float4*>(sm + (kt % STAGES_T) * STAGE_FLOATS);
        const float4* A = Abase + (size_t)kt * 1024;
        const float4* Bt = Bbase + ((size_t)kt * 2 + nt2) * 1024;
#pragma unroll
        for (int i = 0; i < 4; i++) cp_async16(s + tid + i * 256, A + tid + i * 256);
        cp_async16(s + 1024 + tid, Bt + half * 256 + tid);
        cp_async16(s + 1280 + tid, Bt + 512 + half * 256 + tid);
    };
    auto issueG = [&](int g) {
        int kt0 = g * 2;
        if (kt0 < KT) issue(kt0);
        if (kt0 + 1 < KT) issue(kt0 + 1);
    };

    auto compute = [&](int stage) {
        const float* sA = sm + stage * STAGE_FLOATS;
        const float* sB = sm + stage * STAGE_FLOATS + 4096;
        float4 bh[2], bl[2];
#pragma unroll
        for (int ni = 0; ni < 2; ni++) {
            int nsl = wn * 2 + ni;
            bh[ni] = *reinterpret_cast<const float4*>(sB + (nsl * 32 + lane) * 4);
            bl[ni] = *reinterpret_cast<const float4*>(sB + 1024 + (nsl * 32 + lane) * 4);
        }
#pragma unroll
        for (int ks = 0; ks < 2; ks++) {
#pragma unroll
            for (int mi = 0; mi < 4; mi++) {
                int ms = wm * 4 + mi;
                float4 a4h = *reinterpret_cast<const float4*>(sA + ((ms * 2 + ks) * 32 + lane) * 4);
                float4 a4l = *reinterpret_cast<const float4*>(sA + 2048 + ((ms * 2 + ks) * 32 + lane) * 4);
                uint32_t ah[4] = {__float_as_uint(a4h.x), __float_as_uint(a4h.y),
                                  __float_as_uint(a4h.z), __float_as_uint(a4h.w)};
                uint32_t al[4] = {__float_as_uint(a4l.x), __float_as_uint(a4l.y),
                                  __float_as_uint(a4l.z), __float_as_uint(a4l.w)};
#pragma unroll
                for (int ni = 0; ni < 2; ni++) {
                    float* a4 = &acc[(mi * 2 + ni) * 4];
                    uint32_t bhk0 = (ks == 0) ? __float_as_uint(bh[ni].x) : __float_as_uint(bh[ni].z);
                    uint32_t bhk1 = (ks == 0) ? __float_as_uint(bh[ni].y) : __float_as_uint(bh[ni].w);
                    uint32_t blk0 = (ks == 0) ? __float_as_uint(bl[ni].x) : __float_as_uint(bl[ni].z);
                    uint32_t blk1 = (ks == 0) ? __float_as_uint(bl[ni].y) : __float_as_uint(bl[ni].w);
                    mma8(a4, al, bhk0, bhk1);
                    mma8(a4, ah, blk0, blk1);
                    mma8(a4, ah, bhk0, bhk1);
                }
            }
        }
    };

    auto fold = [&]() {
#pragma unroll
        for (int i = 0; i < 32; i++) { mst[i] = __fadd_rn(mst[i], acc[i]); acc[i] = 0.f; }
    };

    const int NG = (KT + 1) >> 1;
    issueG(0); cp_commit();
    issueG(1); cp_commit();

    for (int g = 0; g < NG; g++) {
        cp_wait<1>();
        __syncthreads();
        int kt = g * 2;
        compute(kt % STAGES_T);
        if (((kt + 1) % FOLD) == 0 || kt == KT - 1) fold();
        if (kt + 1 < KT) {
            compute((kt + 1) % STAGES_T);
            if (((kt + 2) % FOLD) == 0 || kt + 1 == KT - 1) fold();
        }
        __syncthreads();
        issueG(g + 2);
        cp_commit();
    }

    float* Cb = C + (long long)b * M * 256;
#pragma unroll
    for (int mi = 0; mi < 4; mi++) {
#pragma unroll
        for (int ni = 0; ni < 2; ni++) {
            int rB = mt * 128 + wm * 64 + mi * 16 + gid;
            int cB = nt4 * 64 + wn * 16 + ni * 8 + tig * 2;
#pragma unroll
            for (int rr = 0; rr < 2; rr++) {
                int r = rB + rr * 8;
                if (r < M) {
#pragma unroll
                    for (int c2 = 0; c2 < 2; c2++) {
                        int c = cB + c2;
                        float v = mst[(mi * 2 + ni) * 4 + rr * 2 + c2];
                        size_t idx = (size_t)r * 256 + c;
                        if (MODE == 1) {
                            Cb[idx] = 1.f / (1.f + expf(-v));
                        } else if (MODE == 2) {
                            float z = 1.f / (1.f + expf(-(v + bias[c])));
                            Cb[idx] = (1.f - z) * aux1[idx] + z * aux2[idx];
                        } else {
                            float t = tanhf(v);
                            float z = aux1[idx];
                            Cb[idx] = (1.f - z) * aux2[idx] + z * t;
                        }
                    }
                }
            }
        }
    }
}

// ---------------- fused weight transpose ----------------
__global__ void k_transW(const float* __restrict__ Wf, const float* __restrict__ Wz,
                         const float* __restrict__ Wr, const float* __restrict__ Wt,
                         float* __restrict__ WfT, float* __restrict__ WzT,
                         float* __restrict__ WrT, float* __restrict__ WtT)
{
    __shared__ float t[32][33];
    int x = threadIdx.x, y = threadIdx.y;
    const float* srcs[4] = {Wf, Wz, Wr, Wt};
    float* dsts[4] = {WfT, WzT, WrT, WtT};
    const int Cs[4] = {1024, 512, 512, 512};
#pragma unroll
    for (int w = 0; w < 4; w++) {
        int C = Cs[w];
        const int R = 256;
        if (blockIdx.x * 32 >= C) continue;
        int bx = blockIdx.x * 32, by = blockIdx.y * 32;
        __syncthreads();
#pragma unroll
        for (int j = 0; j < 32; j += 8) {
            int r = by + y + j, c = bx + x;
            t[y + j][x] = srcs[w][(size_t)r * C + c];
        }
        __syncthreads();
#pragma unroll
        for (int j = 0; j < 32; j += 8) {
            int r = bx + y + j, c = by + x;
            dsts[w][(size_t)r * R + c] = t[x][y + j];
        }
    }
}

// ---------------- host side ----------------
static void run_c128(const float* pA, const float* pB, float* C, int M, int MT, int KT,
                     const float* cmean, const float* Ssum)
{
    cudaFuncSetAttribute(gemm_frag_c128, cudaFuncAttributeMaxDynamicSharedMemorySize, FRAG_SMEM_C);
    dim3 grid(2, MT, BB);
    gemm_frag_c128<<<grid, 256, FRAG_SMEM_C>>>(pA, pB, C, M, MT, KT, cmean, Ssum);
}
static void run_c64(const float* pA, const float* pB, float* C, int M, int MT, int KT,
                    const float* cmean, const float* Ssum)
{
    cudaFuncSetAttribute(gemm_frag_c64, cudaFuncAttributeMaxDynamicSharedMemorySize, FRAG_SMEM_T);
    dim3 grid(4, MT, BB);
    gemm_frag_c64<<<grid, 256, FRAG_SMEM_T>>>(pA, pB, C, M, MT, KT, cmean, Ssum);
}

template<int MODE, int FOLD>
static void run_frag(const float* pA, const float* pB, float* C, int M, int MT, int KT, int batch,
                     const float* bias, const float* a1, const float* a2)
{
    cudaFuncSetAttribute(gemm_frag<MODE, FOLD>, cudaFuncAttributeMaxDynamicSharedMemorySize, FRAG_SMEM_T);
    dim3 grid(4, MT, batch);
    gemm_frag<MODE, FOLD><<<grid, 256, FRAG_SMEM_T>>>(pA, pB, C, M, MT, KT, bias, a1, a2);
}

extern "C" void kernel_launch(void* const* d_in, const int* in_sizes, int n_in,
                              void* d_out, int out_size)
{
    const float* node_feature = (const float*)d_in[0];
    const float* node2edge    = (const float*)d_in[1];
    const float* edge2node    = (const float*)d_in[2];
    const float* Wz = (const float*)d_in[3];
    const float* Wr = (const float*)d_in[4];
    const float* Wt = (const float*)d_in[5];
    const float* Wf = (const float*)d_in[6];
    const float* bf = (const float*)d_in[7];
    float* out = (float*)d_out;

    float *pA1, *pA2, *pA3, *pA4, *pBnf, *pBt1, *pBt2, *pAct, *pWf, *pWz, *pWr, *pWt;
    float *c1, *c2, *c3, *c4, *Snf, *St1, *St2, *Spart;
    float *tmp1, *tmp2, *bwP, *fwP, *agg, *zg, *rg, *nf1;
    float *WfT, *WzT, *WrT, *WtT;
    cudaGetSymbolAddress((void**)&pA1, g_pA1);
    cudaGetSymbolAddress((void**)&pA2, g_pA2);
    cudaGetSymbolAddress((void**)&pA3, g_pA3);
    cudaGetSymbolAddress((void**)&pA4, g_pA4);
    cudaGetSymbolAddress((void**)&pBnf, g_pBnf);
    cudaGetSymbolAddress((void**)&pBt1, g_pBt1);
    cudaGetSymbolAddress((void**)&pBt2, g_pBt2);
    cudaGetSymbolAddress((void**)&pAct, g_pAct);
    cudaGetSymbolAddress((void**)&pWf, g_pWf);
    cudaGetSymbolAddress((void**)&pWz, g_pWz);
    cudaGetSymbolAddress((void**)&pWr, g_pWr);
    cudaGetSymbolAddress((void**)&pWt, g_pWt);
    cudaGetSymbolAddress((void**)&c1, g_c1);
    cudaGetSymbolAddress((void**)&c2, g_c2);
    cudaGetSymbolAddress((void**)&c3, g_c3);
    cudaGetSymbolAddress((void**)&c4, g_c4);
    cudaGetSymbolAddress((void**)&Snf, g_Snf);
    cudaGetSymbolAddress((void**)&St1, g_St1);
    cudaGetSymbolAddress((void**)&St2, g_St2);
    cudaGetSymbolAddress((void**)&Spart, g_Spart);
    cudaGetSymbolAddress((void**)&tmp1, g_tmp1);
    cudaGetSymbolAddress((void**)&tmp2, g_tmp2);
    cudaGetSymbolAddress((void**)&bwP,  g_bw);
    cudaGetSymbolAddress((void**)&fwP,  g_fw);
    cudaGetSymbolAddress((void**)&agg,  g_agg);
    cudaGetSymbolAddress((void**)&zg,   g_zg);
    cudaGetSymbolAddress((void**)&rg,   g_rg);
    cudaGetSymbolAddress((void**)&nf1,  g_nf1);
    cudaGetSymbolAddress((void**)&WfT,  g_WfT);
    cudaGetSymbolAddress((void**)&WzT,  g_WzT);
    cudaGetSymbolAddress((void**)&WrT,  g_WrT);
    cudaGetSymbolAddress((void**)&WtT,  g_WtT);

    // weights: one fused transpose launch, then B-images
    k_transW<<<dim3(32, 8), dim3(32, 8)>>>(Wf, Wz, Wr, Wt, WfT, WzT, WrT, WtT);
    k_packB<<<dim3(KTF, 2, 1), 256>>>(WfT, pWf, 4 * HH, KTF);
    k_packB<<<dim3(KTG, 2, 1), 256>>>(WzT, pWz, 2 * HH, KTG);
    k_packB<<<dim3(KTG, 2, 1), 256>>>(WrT, pWr, 2 * HH, KTG);
    k_packB<<<dim3(KTG, 2, 1), 256>>>(WtT, pWt, 2 * HH, KTG);

    const long long sPQ = (long long)EE * NN;
    const int MR = BB * NN;

    // row means for the 4 A operands
    k_rowmean0<<<dim3((EE + 7) / 8, BB), 256>>>(node2edge, c1, EE, NN, NN, sPQ);
    k_rowmean1<<<dim3((EE + 255) / 256, BB), 256>>>(edge2node, c2, EE, NN, EE, sPQ);
    k_rowmean0<<<dim3((NN + 7) / 8, BB), 256>>>(edge2node, c3, NN, EE, EE, sPQ);
    k_rowmean1<<<dim3((NN + 255) / 256, BB), 256>>>(node2edge, c4, NN, EE, NN, sPQ);

    // pack CENTERED adjacency fragment images (reused both hops)
    k_packA<0><<<dim3(KT12, MT12, BB), 256>>>(node2edge, c1, pA1, EE, NN, NN, sPQ, MT12, KT12);
    k_packA<1><<<dim3(KT12, MT12, BB), 256>>>(edge2node, c2, pA2, EE, NN, EE, sPQ, MT12, KT12);
    k_packA<0><<<dim3(KT34, MT34, BB), 256>>>(edge2node, c3, pA3, NN, EE, EE, sPQ, MT34, KT34);
    k_packA<1><<<dim3(KT34, MT34, BB), 256>>>(node2edge, c4, pA4, NN, EE, NN, sPQ, MT34, KT34);

    const float* nfIn = node_feature;
    for (int hop = 0; hop < 2; hop++) {
        float* nfOut = (hop == 1) ? out : nf1;

        k_packB<<<dim3(KT12, 2, BB), 256>>>(nfIn, pBnf, NN, KT12);
        k_colsum_part<<<dim3(CSUM_CH, BB), 256>>>(nfIn, Spart, NN);
        k_colsum_red<<<dim3(1, BB), 256>>>(Spart, Snf);

        // GEMM1/2: large grid -> 128x128 centered kernel
        run_c128(pA1, pBnf, tmp1, EE, MT12, KT12, c1, Snf);
        run_c128(pA2, pBnf, tmp2, EE, MT12, KT12, c2, Snf);

        k_packB<<<dim3(KT34, 2, BB), 256>>>(tmp1, pBt1, EE, KT34);
        k_packB<<<dim3(KT34, 2, BB), 256>>>(tmp2, pBt2, EE, KT34);
        k_colsum_part<<<dim3(CSUM_CH, BB), 256>>>(tmp1, Spart, EE);
        k_colsum_red<<<dim3(1, BB), 256>>>(Spart, St1);
        k_colsum_part<<<dim3(CSUM_CH, BB), 256>>>(tmp2, Spart, EE);
        k_colsum_red<<<dim3(1, BB), 256>>>(Spart, St2);

        // GEMM3/4: small grid -> 128x64 centered kernel (256 CTAs)
        run_c64(pA3, pBt1, bwP, NN, MT34, KT34, c3, St1);
        run_c64(pA4, pBt2, fwP, NN, MT34, KT34, c4, St2);

        // gated fusion (small path unchanged)
        k_packA_f<0><<<dim3(KTF, MTS), 256>>>(fwP, bwP, nullptr, pAct, KTF);
        run_frag<2, 1>(pAct, pWf, agg, MR, MTS, KTF, 1, bf, fwP, bwP);

        // GRU step
        k_packA_f<1><<<dim3(KTG, MTS), 256>>>(nfIn, agg, nullptr, pAct, KTG);
        run_frag<1, 1>(pAct, pWz, zg, MR, MTS, KTG, 1, nullptr, nullptr, nullptr);
        run_frag<1, 1>(pAct, pWr, rg, MR, MTS, KTG, 1, nullptr, nullptr, nullptr);
        k_packA_f<2><<<dim3(KTG, MTS), 256>>>(rg, nfIn, agg, pAct, KTG);
        run_frag<3, 1>(pAct, pWt, nfOut, MR, MTS, KTG, 1, nullptr, zg, nfIn);

        nfIn = nfOut;
    }
}

// round 15
// speedup vs baseline: 1.0309x; 1.0064x over previous
#include <cuda_runtime.h>
#include <cstdint>
#include <math.h>

// ---------------- problem constants ----------------
#define BB 8
#define NN 1000
#define EE 4000
#define HH 256

#define MT12 32
#define KT12 63
#define MT34 8
#define KT34 250

#define MTS 63
#define KTF 64
#define KTG 32

#define PA12_SZ (MT12*KT12*4096*BB)
#define PA34_SZ (MT34*KT34*4096*BB)
#define PB_NF_SZ (KT12*2*4096*BB)
#define PB_T_SZ  (KT34*2*4096*BB)
#define PACT_SZ  (MTS*KTF*4096)

#define CSUM_CH 16

// ---------------- scratch ----------------
__device__ float g_pA1[PA12_SZ];
__device__ float g_pA2[PA12_SZ];
__device__ float g_pA3[PA34_SZ];
__device__ float g_pA4[PA34_SZ];
__device__ float g_pBnf[PB_NF_SZ];
__device__ float g_pBt1[PB_T_SZ];
__device__ float g_pBt2[PB_T_SZ];
__device__ float g_pAct[PACT_SZ];
__device__ float g_pWf[KTF*2*4096];
__device__ float g_pWz[KTG*2*4096];
__device__ float g_pWr[KTG*2*4096];
__device__ float g_pWt[KTG*2*4096];

__device__ float g_c1[BB*EE];
__device__ float g_c2[BB*EE];
__device__ float g_c3[BB*NN];
__device__ float g_c4[BB*NN];
__device__ float g_Snf[BB*256];
__device__ float g_St1[BB*256];
__device__ float g_St2[BB*256];
__device__ float g_Spart[CSUM_CH*BB*256];

__device__ float g_tmp1[BB*EE*HH];
__device__ float g_tmp2[BB*EE*HH];
__device__ float g_bw  [BB*NN*HH];
__device__ float g_fw  [BB*NN*HH];
__device__ float g_agg [BB*NN*HH];
__device__ float g_zg  [BB*NN*HH];
__device__ float g_rg  [BB*NN*HH];
__device__ float g_nf1 [BB*NN*HH];
__device__ float g_WfT [4*HH*HH];
__device__ float g_WzT [2*HH*HH];
__device__ float g_WrT [2*HH*HH];
__device__ float g_WtT [2*HH*HH];

// ---------------- helpers ----------------
__device__ __forceinline__ uint32_t f2tf(float f) {
    uint32_t u; asm("cvt.rna.tf32.f32 %0, %1;" : "=r"(u) : "f"(f)); return u;
}

__device__ __forceinline__ void split2(float x, float& h, float& l) {
    uint32_t hu = f2tf(x);
    h = __uint_as_float(hu);
    float r1 = __fadd_rn(x, -h);
    uint32_t lu = f2tf(r1);
    l = __uint_as_float(lu);
}

__device__ __forceinline__ void mma8(float* d, const uint32_t* a, uint32_t b0, uint32_t b1) {
    asm volatile(
        "mma.sync.aligned.m16n8k8.row.col.f32.tf32.tf32.f32 "
        "{%0,%1,%2,%3},{%4,%5,%6,%7},{%8,%9},{%0,%1,%2,%3};"
        : "+f"(d[0]), "+f"(d[1]), "+f"(d[2]), "+f"(d[3])
        : "r"(a[0]), "r"(a[1]), "r"(a[2]), "r"(a[3]), "r"(b0), "r"(b1));
}

__device__ __forceinline__ void cp_async16(float4* smem_ptr, const float4* gptr) {
    uint32_t s = (uint32_t)__cvta_generic_to_shared(smem_ptr);
    asm volatile("cp.async.cg.shared.global [%0], [%1], 16;" :: "r"(s), "l"(gptr));
}
__device__ __forceinline__ void cp_commit() {
    asm volatile("cp.async.commit_group;");
}
template<int N>
__device__ __forceinline__ void cp_wait() {
    asm volatile("cp.async.wait_group %0;" :: "n"(N));
}

__device__ __forceinline__ int a_frag_off(int mRel, int kRel) {
    int ms = mRel >> 4;
    int ks2 = kRel >> 3;
    int lane = (mRel & 7) * 4 + (kRel & 3);
    int areg = ((kRel >> 2) & 1) * 2 + ((mRel >> 3) & 1);
    return (((ms * 2) + ks2) * 32 + lane) * 4 + areg;
}
__device__ __forceinline__ int b_frag_off(int kRel, int nRel) {
    int ns = nRel >> 3;
    int lane = (nRel & 7) * 4 + (kRel & 3);
    int breg = ((kRel >> 3) & 1) * 2 + ((kRel >> 2) & 1);
    return (ns * 32 + lane) * 4 + breg;
}

// ---------------- mean / colsum kernels ----------------
__global__ void __launch_bounds__(256)
k_rowmean0(const float* __restrict__ src, float* __restrict__ c,
           int M, int K, int lda, long long sB)
{
    int b = blockIdx.y;
    int row = blockIdx.x * 8 + (threadIdx.x >> 5);
    int lane = threadIdx.x & 31;
    if (row >= M) return;
    const float* S = src + (long long)b * sB + (size_t)row * lda;
    float s = 0.f;
    for (int k = lane; k < K; k += 32) s += S[k];
#pragma unroll
    for (int o = 16; o; o >>= 1) s += __shfl_xor_sync(0xffffffffu, s, o);
    if (lane == 0) c[(size_t)b * M + row] = s * (1.0f / K);
}

__global__ void __launch_bounds__(256)
k_rowmean1(const float* __restrict__ src, float* __restrict__ c,
           int M, int K, int lda, long long sB)
{
    int b = blockIdx.y;
    int m = blockIdx.x * 256 + threadIdx.x;
    if (m >= M) return;
    const float* S = src + (long long)b * sB + m;
    float s = 0.f;
    for (int k = 0; k < K; k++) s += S[(size_t)k * lda];
    c[(size_t)b * M + m] = s * (1.0f / K);
}

__global__ void __launch_bounds__(256)
k_colsum_part(const float* __restrict__ B, float* __restrict__ part, int K)
{
    int b = blockIdx.y, ch = blockIdx.x, h = threadIdx.x;
    int chunk = (K + CSUM_CH - 1) / CSUM_CH;
    int k0 = ch * chunk, k1 = min(K, k0 + chunk);
    const float* p = B + (long long)b * K * 256 + h;
    float s = 0.f;
    for (int k = k0; k < k1; k++) s += p[(size_t)k * 256];
    part[((size_t)b * CSUM_CH + ch) * 256 + h] = s;
}
__global__ void __launch_bounds__(256)
k_colsum_red(const float* __restrict__ part, float* __restrict__ S)
{
    int b = blockIdx.y, h = threadIdx.x;
    float s = 0.f;
#pragma unroll
    for (int ch = 0; ch < CSUM_CH; ch++) s += part[((size_t)b * CSUM_CH + ch) * 256 + h];
    S[(size_t)b * 256 + h] = s;
}

// ---------------- pack kernels ----------------
template<int TRANSA>
__global__ void __launch_bounds__(256)
k_packA(const float* __restrict__ src, const float* __restrict__ cmean, float* __restrict__ dst,
        int M, int K, int lda, long long sSrc, int MT, int KT)
{
    __shared__ float img[4096];
    int kt = blockIdx.x, mt = blockIdx.y, b = blockIdx.z;
    const float* S = src + (long long)b * sSrc;
    const float* cm = cmean + (long long)b * M;
    int m0 = mt * 128, k0 = kt * 16;
    int tid = threadIdx.x;
#pragma unroll
    for (int it = 0; it < 2; it++) {
        int linear = tid + it * 256;
        if (TRANSA == 0) {
            int row = linear >> 2, c4 = (linear & 3) << 2;
            int gm = m0 + row, gk = k0 + c4;
            float cv = (gm < M) ? cm[gm] : 0.f;
#pragma unroll
            for (int j = 0; j < 4; j++) {
                float val = 0.f;
                if (gm < M && gk + j < K)
                    val = __fadd_rn(S[(size_t)gm * lda + gk + j], -cv);
                float h, l;
                split2(val, h, l);
                int off = a_frag_off(row, c4 + j);
                img[off] = h; img[2048 + off] = l;
            }
        } else {
            int kk = linear >> 5, m4 = (linear & 31) << 2;
            int gk = k0 + kk, gm = m0 + m4;
#pragma unroll
            for (int j = 0; j < 4; j++) {
                float val = 0.f;
                if (gk < K && gm + j < M)
                    val = __fadd_rn(S[(size_t)gk * lda + gm + j], -cm[gm + j]);
                float h, l;
                split2(val, h, l);
                int off = a_frag_off(m4 + j, kk);
                img[off] = h; img[2048 + off] = l;
            }
        }
    }
    __syncthreads();
    float4* D = reinterpret_cast<float4*>(dst + (((long long)b * MT + mt) * KT + kt) * 4096);
    const float4* I = reinterpret_cast<const float4*>(img);
#pragma unroll
    for (int i = 0; i < 4; i++) D[tid + i * 256] = I[tid + i * 256];
}

template<int SRC>
__global__ void __launch_bounds__(256)
k_packA_f(const float* __restrict__ s1, const float* __restrict__ s2, const float* __restrict__ s3,
          float* __restrict__ dst, int KT)
{
    __shared__ float img[4096];
    int kt = blockIdx.x, mt = blockIdx.y;
    int m0 = mt * 128, k0 = kt * 16;
    int tid = threadIdx.x;
#pragma unroll
    for (int it = 0; it < 2; it++) {
        int linear = tid + it * 256;
        int row = linear >> 2, c4 = (linear & 3) << 2;
        int gm = m0 + row;
#pragma unroll
        for (int j = 0; j < 4; j++) {
            int gk = k0 + c4 + j;
            float val = 0.f;
            if (gm < BB * NN) {
                if (SRC == 0) {
                    int feat = gk >> 8, hcol = gk & 255;
                    float f = s1[(size_t)gm * 256 + hcol];
                    float b = s2[(size_t)gm * 256 + hcol];
                    val = (feat == 0) ? f : (feat == 1) ? b : (feat == 2) ? f * b : f - b;
                } else if (SRC == 1) {
                    val = (gk < 256) ? s1[(size_t)gm * 256 + gk]
                                     : s2[(size_t)gm * 256 + (gk - 256)];
                } else {
                    val = (gk < 256) ? s1[(size_t)gm * 256 + gk] * s2[(size_t)gm * 256 + gk]
                                     : s3[(size_t)gm * 256 + (gk - 256)];
                }
            }
            float h, l;
            split2(val, h, l);
            int off = a_frag_off(row, c4 + j);
            img[off] = h; img[2048 + off] = l;
        }
    }
    __syncthreads();
    float4* D = reinterpret_cast<float4*>(dst + ((long long)mt * KT + kt) * 4096);
    const float4* I = reinterpret_cast<const float4*>(img);
#pragma unroll
    for (int i = 0; i < 4; i++) D[tid + i * 256] = I[tid + i * 256];
}

__global__ void __launch_bounds__(256)
k_packB(const float* __restrict__ src, float* __restrict__ dst, int K, int KT)
{
    __shared__ float img[4096];
    int kt = blockIdx.x, nt = blockIdx.y, b = blockIdx.z;
    const float* S = src + (long long)b * K * 256;
    int k0 = kt * 16, n0 = nt * 128;
    int tid = threadIdx.x;
#pragma unroll
    for (int it = 0; it < 2; it++) {
        int linear = tid + it * 256;
        int kr = linear >> 5, n4 = (linear & 31) << 2;
        int gk = k0 + kr;
        float4 v = make_float4(0.f, 0.f, 0.f, 0.f);
        if (gk < K) v = *reinterpret_cast<const float4*>(S + (size_t)gk * 256 + n0 + n4);
        const float* pv = &v.x;
#pragma unroll
        for (int j = 0; j < 4; j++) {
            float h, l;
            split2(pv[j], h, l);
            int off = b_frag_off(kr, n4 + j);
            img[off] = h; img[2048 + off] = l;
        }
    }
    __syncthreads();
    float4* D = reinterpret_cast<float4*>(dst + (((long long)b * KT + kt) * 2 + nt) * 4096);
    const float4* I = reinterpret_cast<const float4*>(img);
#pragma unroll
    for (int i = 0; i < 4; i++) D[tid + i * 256] = I[tid + i * 256];
}

// ---------------- centered big GEMM, 128x64 tile (ALL big GEMMs) ----------------
// out = (A-c)B + c*S ; acc[32] only (no master accumulator; centered partial sums stay small)
// ~80 regs -> genuinely 2 CTAs/SM (the 128x128 variant spilled under launch_bounds(256,2))
#define STAGES_T 4
#define STAGE_FLOATS 6144
#define FRAG_SMEM_T (STAGES_T*STAGE_FLOATS*4)   // 98304 bytes

__global__ void __launch_bounds__(256, 2)
gemm_frag_c64(const float* __restrict__ pA, const float* __restrict__ pB, float* __restrict__ C,
              int M, int MT, int KT,
              const float* __restrict__ cmean, const float* __restrict__ Ssum)
{
    extern __shared__ float sm[];
    const int tid = threadIdx.x;
    const int nt4 = blockIdx.x, mt = blockIdx.y, b = blockIdx.z;
    const int nt2 = nt4 >> 1, half = nt4 & 1;
    const float4* Abase = reinterpret_cast<const float4*>(pA) + ((long long)b * MT + mt) * KT * 1024;
    const float4* Bbase = reinterpret_cast<const float4*>(pB) + (long long)b * KT * 2048;

    const int lane = tid & 31, warp = tid >> 5;
    const int wm = warp >> 2, wn = warp & 3;
    const int gid = lane >> 2, tig = lane & 3;

    float acc[32];
#pragma unroll
    for (int i = 0; i < 32; i++) acc[i] = 0.f;

    auto issue = [&](int kt) {
        float4* s = reinterpret_cast<float4*>(sm + (kt % STAGES_T) * STAGE_FLOATS);
        const float4* A = Abase + (size_t)kt * 1024;
        const float4* Bt = Bbase + ((size_t)kt * 2 + nt2) * 1024;
#pragma unroll
        for (int i = 0; i < 4; i++) cp_async16(s + tid + i * 256, A + tid + i * 256);
        cp_async16(s + 1024 + tid, Bt + half * 256 + tid);
        cp_async16(s + 1280 + tid, Bt + 512 + half * 256 + tid);
    };
    auto issueG = [&](int g) {
        int kt0 = g * 2;
        if (kt0 < KT) issue(kt0);
        if (kt0 + 1 < KT) issue(kt0 + 1);
    };

    auto compute = [&](int stage) {
        const float* sA = sm + stage * STAGE_FLOATS;
        const float* sB = sm + stage * STAGE_FLOATS + 4096;
        float4 bh[2], bl[2];
#pragma unroll
        for (int ni = 0; ni < 2; ni++) {
            int nsl = wn * 2 + ni;
            bh[ni] = *reinterpret_cast<const float4*>(sB + (nsl * 32 + lane) * 4);
            bl[ni] = *reinterpret_cast<const float4*>(sB + 1024 + (nsl * 32 + lane) * 4);
        }
#pragma unroll
        for (int ks = 0; ks < 2; ks++) {
#pragma unroll
            for (int mi = 0; mi < 4; mi++) {
                int ms = wm * 4 + mi;
                float4 a4h = *reinterpret_cast<const float4*>(sA + ((ms * 2 + ks) * 32 + lane) * 4);
                float4 a4l = *reinterpret_cast<const float4*>(sA + 2048 + ((ms * 2 + ks) * 32 + lane) * 4);
                uint32_t ah[4] = {__float_as_uint(a4h.x), __float_as_uint(a4h.y),
                                  __float_as_uint(a4h.z), __float_as_uint(a4h.w)};
                uint32_t al[4] = {__float_as_uint(a4l.x), __float_as_uint(a4l.y),
                                  __float_as_uint(a4l.z), __float_as_uint(a4l.w)};
#pragma unroll
                for (int ni = 0; ni < 2; ni++) {
                    float* a4 = &acc[(mi * 2 + ni) * 4];
                    uint32_t bhk0 = (ks == 0) ? __float_as_uint(bh[ni].x) : __float_as_uint(bh[ni].z);
                    uint32_t bhk1 = (ks == 0) ? __float_as_uint(bh[ni].y) : __float_as_uint(bh[ni].w);
                    uint32_t blk0 = (ks == 0) ? __float_as_uint(bl[ni].x) : __float_as_uint(bl[ni].z);
                    uint32_t blk1 = (ks == 0) ? __float_as_uint(bl[ni].y) : __float_as_uint(bl[ni].w);
                    mma8(a4, al, bhk0, bhk1);
                    mma8(a4, ah, blk0, blk1);
                    mma8(a4, ah, bhk0, bhk1);
                }
            }
        }
    };

    const int NG = (KT + 1) >> 1;
    issueG(0); cp_commit();
    issueG(1); cp_commit();

    for (int g = 0; g < NG; g++) {
        cp_wait<1>();
        __syncthreads();
        int kt = g * 2;
        compute(kt % STAGES_T);
        if (kt + 1 < KT) compute((kt + 1) % STAGES_T);
        __syncthreads();
        issueG(g + 2);
        cp_commit();
    }

    float* Cb = C + (long long)b * M * 256;
    const float* cm = cmean + (long long)b * M;
    const float* Sv = Ssum + (long long)b * 256;
#pragma unroll
    for (int mi = 0; mi < 4; mi++) {
#pragma unroll
        for (int ni = 0; ni < 2; ni++) {
            int rB = mt * 128 + wm * 64 + mi * 16 + gid;
            int cB = nt4 * 64 + wn * 16 + ni * 8 + tig * 2;
#pragma unroll
            for (int rr = 0; rr < 2; rr++) {
                int r = rB + rr * 8;
                if (r < M) {
                    float cv = cm[r];
#pragma unroll
                    for (int c2 = 0; c2 < 2; c2++) {
                        int c = cB + c2;
                        float v = acc[(mi * 2 + ni) * 4 + rr * 2 + c2];
                        Cb[(size_t)r * 256 + c] = __fadd_rn(v, __fmul_rn(cv, Sv[c]));
                    }
                }
            }
        }
    }
}

// ---------------- small GEMM (unchanged): 128x64 tile, mst FOLD=1 ----------------
template<int MODE, int FOLD>
__global__ void __launch_bounds__(256, 2)
gemm_frag(const float* __restrict__ pA, const float* __restrict__ pB, float* __restrict__ C,
          int M, int MT, int KT,
          const float* __restrict__ bias,
          const float* __restrict__ aux1, const float* __restrict__ aux2)
{
    extern __shared__ float sm[];
    const int tid = threadIdx.x;
    const int nt4 = blockIdx.x, mt = blockIdx.y, b = blockIdx.z;
    const int nt2 = nt4 >> 1, half = nt4 & 1;
    const float4* Abase = reinterpret_cast<const float4*>(pA) + ((long long)b * MT + mt) * KT * 1024;
    const float4* Bbase = reinterpret_cast<const float4*>(pB) + (long long)b * KT * 2048;

    const int lane = tid & 31, warp = tid >> 5;
    const int wm = warp >> 2, wn = warp & 3;
    const int gid = lane >> 2, tig = lane & 3;

    float acc[32], mst[32];
#pragma unroll
    for (int i = 0; i < 32; i++) { acc[i] = 0.f; mst[i] = 0.f; }

    auto issue = [&](int kt) {
        float4* s = reinterpret_cast<float4*>(sm + (kt % STAGES_T) * STAGE_FLOATS);
        const float4* A = Abase + (size_t)kt * 1024;
        const float4* Bt = Bbase + ((size_t)kt * 2 + nt2) * 1024;
#pragma unroll
        for (int i = 0; i < 4; i++) cp_async16(s + tid + i * 256, A + tid + i * 256);
        cp_async16(s + 1024 + tid, Bt + half * 256 + tid);
        cp_async16(s + 1280 + tid, Bt + 512 + half * 256 + tid);
    };
    auto issueG = [&](int g) {
        int kt0 = g * 2;
        if (kt0 < KT) issue(kt0);
        if (kt0 + 1 < KT) issue(kt0 + 1);
    };

    auto compute = [&](int stage) {
        const float* sA = sm + stage * STAGE_FLOATS;
        const float* sB = sm + stage * STAGE_FLOATS + 4096;
        float4 bh[2], bl[2];
#pragma unroll
        for (int ni = 0; ni < 2; ni++) {
            int nsl = wn * 2 + ni;
            bh[ni] = *reinterpret_cast<const float4*>(sB + (nsl * 32 + lane) * 4);
            bl[ni] = *reinterpret_cast<const float4*>(sB + 1024 + (nsl * 32 + lane) * 4);
        }
#pragma unroll
        for (int ks = 0; ks < 2; ks++) {
#pragma unroll
            for (int mi = 0; mi < 4; mi++) {
                int ms = wm * 4 + mi;
                float4 a4h = *reinterpret_cast<const float4*>(sA + ((ms * 2 + ks) * 32 + lane) * 4);
                float4 a4l = *reinterpret_cast<const float4*>(sA + 2048 + ((ms * 2 + ks) * 32 + lane) * 4);
                uint32_t ah[4] = {__float_as_uint(a4h.x), __float_as_uint(a4h.y),
                                  __float_as_uint(a4h.z), __float_as_uint(a4h.w)};
                uint32_t al[4] = {__float_as_uint(a4l.x), __float_as_uint(a4l.y),
                                  __float_as_uint(a4l.z), __float_as_uint(a4l.w)};
#pragma unroll
                for (int ni = 0; ni < 2; ni++) {
                    float* a4 = &acc[(mi * 2 + ni) * 4];
                    uint32_t bhk0 = (ks == 0) ? __float_as_uint(bh[ni].x) : __float_as_uint(bh[ni].z);
                    uint32_t bhk1 = (ks == 0) ? __float_as_uint(bh[ni].y) : __float_as_uint(bh[ni].w);
                    uint32_t blk0 = (ks == 0) ? __float_as_uint(bl[ni].x) : __float_as_uint(bl[ni].z);
                    uint32_t blk1 = (ks == 0) ? __float_as_uint(bl[ni].y) : __float_as_uint(bl[ni].w);
                    mma8(a4, al, bhk0, bhk1);
                    mma8(a4, ah, blk0, blk1);
                    mma8(a4, ah, bhk0, bhk1);
                }
            }
        }
    };

    auto fold = [&]() {
#pragma unroll
        for (int i = 0; i < 32; i++) { mst[i] = __fadd_rn(mst[i], acc[i]); acc[i] = 0.f; }
    };

    const int NG = (KT + 1) >> 1;
    issueG(0); cp_commit();
    issueG(1); cp_commit();

    for (int g = 0; g < NG; g++) {
        cp_wait<1>();
        __syncthreads();
        int kt = g * 2;
        compute(kt % STAGES_T);
        if (((kt + 1) % FOLD) == 0 || kt == KT - 1) fold();
        if (kt + 1 < KT) {
            compute((kt + 1) % STAGES_T);
            if (((kt + 2) % FOLD) == 0 || kt + 1 == KT - 1) fold();
        }
        __syncthreads();
        issueG(g + 2);
        cp_commit();
    }

    float* Cb = C + (long long)b * M * 256;
#pragma unroll
    for (int mi = 0; mi < 4; mi++) {
#pragma unroll
        for (int ni = 0; ni < 2; ni++) {
            int rB = mt * 128 + wm * 64 + mi * 16 + gid;
            int cB = nt4 * 64 + wn * 16 + ni * 8 + tig * 2;
#pragma unroll
            for (int rr = 0; rr < 2; rr++) {
                int r = rB + rr * 8;
                if (r < M) {
#pragma unroll
                    for (int c2 = 0; c2 < 2; c2++) {
                        int c = cB + c2;
                        float v = mst[(mi * 2 + ni) * 4 + rr * 2 + c2];
                        size_t idx = (size_t)r * 256 + c;
                        if (MODE == 1) {
                            Cb[idx] = 1.f / (1.f + expf(-v));
                        } else if (MODE == 2) {
                            float z = 1.f / (1.f + expf(-(v + bias[c])));
                            Cb[idx] = (1.f - z) * aux1[idx] + z * aux2[idx];
                        } else {
                            float t = tanhf(v);
                            float z = aux1[idx];
                            Cb[idx] = (1.f - z) * aux2[idx] + z * t;
                        }
                    }
                }
            }
        }
    }
}

// ---------------- fused weight transpose ----------------
__global__ void k_transW(const float* __restrict__ Wf, const float* __restrict__ Wz,
                         const float* __restrict__ Wr, const float* __restrict__ Wt,
                         float* __restrict__ WfT, float* __restrict__ WzT,
                         float* __restrict__ WrT, float* __restrict__ WtT)
{
    __shared__ float t[32][33];
    int x = threadIdx.x, y = threadIdx.y;
    const float* srcs[4] = {Wf, Wz, Wr, Wt};
    float* dsts[4] = {WfT, WzT, WrT, WtT};
    const int Cs[4] = {1024, 512, 512, 512};
#pragma unroll
    for (int w = 0; w < 4; w++) {
        int C = Cs[w];
        const int R = 256;
        if (blockIdx.x * 32 >= C) continue;
        int bx = blockIdx.x * 32, by = blockIdx.y * 32;
        __syncthreads();
#pragma unroll
        for (int j = 0; j < 32; j += 8) {
            int r = by + y + j, c = bx + x;
            t[y + j][x] = srcs[w][(size_t)r * C + c];
        }
        __syncthreads();
#pragma unroll
        for (int j = 0; j < 32; j += 8) {
            int r = bx + y + j, c = by + x;
            dsts[w][(size_t)r * R + c] = t[x][y + j];
        }
    }
}

// ---------------- host side ----------------
static void run_c64(const float* pA, const float* pB, float* C, int M, int MT, int KT,
                    const float* cmean, const float* Ssum)
{
    cudaFuncSetAttribute(gemm_frag_c64, cudaFuncAttributeMaxDynamicSharedMemorySize, FRAG_SMEM_T);
    dim3 grid(4, MT, BB);
    gemm_frag_c64<<<grid, 256, FRAG_SMEM_T>>>(pA, pB, C, M, MT, KT, cmean, Ssum);
}

template<int MODE, int FOLD>
static void run_frag(const float* pA, const float* pB, float* C, int M, int MT, int KT, int batch,
                     const float* bias, const float* a1, const float* a2)
{
    cudaFuncSetAttribute(gemm_frag<MODE, FOLD>, cudaFuncAttributeMaxDynamicSharedMemorySize, FRAG_SMEM_T);
    dim3 grid(4, MT, batch);
    gemm_frag<MODE, FOLD><<<grid, 256, FRAG_SMEM_T>>>(pA, pB, C, M, MT, KT, bias, a1, a2);
}

extern "C" void kernel_launch(void* const* d_in, const int* in_sizes, int n_in,
                              void* d_out, int out_size)
{
    const float* node_feature = (const float*)d_in[0];
    const float* node2edge    = (const float*)d_in[1];
    const float* edge2node    = (const float*)d_in[2];
    const float* Wz = (const float*)d_in[3];
    const float* Wr = (const float*)d_in[4];
    const float* Wt = (const float*)d_in[5];
    const float* Wf = (const float*)d_in[6];
    const float* bf = (const float*)d_in[7];
    float* out = (float*)d_out;

    float *pA1, *pA2, *pA3, *pA4, *pBnf, *pBt1, *pBt2, *pAct, *pWf, *pWz, *pWr, *pWt;
    float *c1, *c2, *c3, *c4, *Snf, *St1, *St2, *Spart;
    float *tmp1, *tmp2, *bwP, *fwP, *agg, *zg, *rg, *nf1;
    float *WfT, *WzT, *WrT, *WtT;
    cudaGetSymbolAddress((void**)&pA1, g_pA1);
    cudaGetSymbolAddress((void**)&pA2, g_pA2);
    cudaGetSymbolAddress((void**)&pA3, g_pA3);
    cudaGetSymbolAddress((void**)&pA4, g_pA4);
    cudaGetSymbolAddress((void**)&pBnf, g_pBnf);
    cudaGetSymbolAddress((void**)&pBt1, g_pBt1);
    cudaGetSymbolAddress((void**)&pBt2, g_pBt2);
    cudaGetSymbolAddress((void**)&pAct, g_pAct);
    cudaGetSymbolAddress((void**)&pWf, g_pWf);
    cudaGetSymbolAddress((void**)&pWz, g_pWz);
    cudaGetSymbolAddress((void**)&pWr, g_pWr);
    cudaGetSymbolAddress((void**)&pWt, g_pWt);
    cudaGetSymbolAddress((void**)&c1, g_c1);
    cudaGetSymbolAddress((void**)&c2, g_c2);
    cudaGetSymbolAddress((void**)&c3, g_c3);
    cudaGetSymbolAddress((void**)&c4, g_c4);
    cudaGetSymbolAddress((void**)&Snf, g_Snf);
    cudaGetSymbolAddress((void**)&St1, g_St1);
    cudaGetSymbolAddress((void**)&St2, g_St2);
    cudaGetSymbolAddress((void**)&Spart, g_Spart);
    cudaGetSymbolAddress((void**)&tmp1, g_tmp1);
    cudaGetSymbolAddress((void**)&tmp2, g_tmp2);
    cudaGetSymbolAddress((void**)&bwP,  g_bw);
    cudaGetSymbolAddress((void**)&fwP,  g_fw);
    cudaGetSymbolAddress((void**)&agg,  g_agg);
    cudaGetSymbolAddress((void**)&zg,   g_zg);
    cudaGetSymbolAddress((void**)&rg,   g_rg);
    cudaGetSymbolAddress((void**)&nf1,  g_nf1);
    cudaGetSymbolAddress((void**)&WfT,  g_WfT);
    cudaGetSymbolAddress((void**)&WzT,  g_WzT);
    cudaGetSymbolAddress((void**)&WrT,  g_WrT);
    cudaGetSymbolAddress((void**)&WtT,  g_WtT);

    // weights: one fused transpose launch, then B-images
    k_transW<<<dim3(32, 8), dim3(32, 8)>>>(Wf, Wz, Wr, Wt, WfT, WzT, WrT, WtT);
    k_packB<<<dim3(KTF, 2, 1), 256>>>(WfT, pWf, 4 * HH, KTF);
    k_packB<<<dim3(KTG, 2, 1), 256>>>(WzT, pWz, 2 * HH, KTG);
    k_packB<<<dim3(KTG, 2, 1), 256>>>(WrT, pWr, 2 * HH, KTG);
    k_packB<<<dim3(KTG, 2, 1), 256>>>(WtT, pWt, 2 * HH, KTG);

    const long long sPQ = (long long)EE * NN;
    const int MR = BB * NN;

    // row means for the 4 A operands
    k_rowmean0<<<dim3((EE + 7) / 8, BB), 256>>>(node2edge, c1, EE, NN, NN, sPQ);
    k_rowmean1<<<dim3((EE + 255) / 256, BB), 256>>>(edge2node, c2, EE, NN, EE, sPQ);
    k_rowmean0<<<dim3((NN + 7) / 8, BB), 256>>>(edge2node, c3, NN, EE, EE, sPQ);
    k_rowmean1<<<dim3((NN + 255) / 256, BB), 256>>>(node2edge, c4, NN, EE, NN, sPQ);

    // pack CENTERED adjacency fragment images (reused both hops)
    k_packA<0><<<dim3(KT12, MT12, BB), 256>>>(node2edge, c1, pA1, EE, NN, NN, sPQ, MT12, KT12);
    k_packA<1><<<dim3(KT12, MT12, BB), 256>>>(edge2node, c2, pA2, EE, NN, EE, sPQ, MT12, KT12);
    k_packA<0><<<dim3(KT34, MT34, BB), 256>>>(edge2node, c3, pA3, NN, EE, EE, sPQ, MT34, KT34);
    k_packA<1><<<dim3(KT34, MT34, BB), 256>>>(node2edge, c4, pA4, NN, EE, NN, sPQ, MT34, KT34);

    const float* nfIn = node_feature;
    for (int hop = 0; hop < 2; hop++) {
        float* nfOut = (hop == 1) ? out : nf1;

        k_packB<<<dim3(KT12, 2, BB), 256>>>(nfIn, pBnf, NN, KT12);
        k_colsum_part<<<dim3(CSUM_CH, BB), 256>>>(nfIn, Spart, NN);
        k_colsum_red<<<dim3(1, BB), 256>>>(Spart, Snf);

        // GEMM1/2: centered 128x64 (grid 4x32x8 = 1024 CTAs)
        run_c64(pA1, pBnf, tmp1, EE, MT12, KT12, c1, Snf);
        run_c64(pA2, pBnf, tmp2, EE, MT12, KT12, c2, Snf);

        k_packB<<<dim3(KT34, 2, BB), 256>>>(tmp1, pBt1, EE, KT34);
        k_packB<<<dim3(KT34, 2, BB), 256>>>(tmp2, pBt2, EE, KT34);
        k_colsum_part<<<dim3(CSUM_CH, BB), 256>>>(tmp1, Spart, EE);
        k_colsum_red<<<dim3(1, BB), 256>>>(Spart, St1);
        k_colsum_part<<<dim3(CSUM_CH, BB), 256>>>(tmp2, Spart, EE);
        k_colsum_red<<<dim3(1, BB), 256>>>(Spart, St2);

        // GEMM3/4: centered 128x64 (grid 4x8x8 = 256 CTAs)
        run_c64(pA3, pBt1, bwP, NN, MT34, KT34, c3, St1);
        run_c64(pA4, pBt2, fwP, NN, MT34, KT34, c4, St2);

        // gated fusion (small path unchanged)
        k_packA_f<0><<<dim3(KTF, MTS), 256>>>(fwP, bwP, nullptr, pAct, KTF);
        run_frag<2, 1>(pAct, pWf, agg, MR, MTS, KTF, 1, bf, fwP, bwP);

        // GRU step
        k_packA_f<1><<<dim3(KTG, MTS), 256>>>(nfIn, agg, nullptr, pAct, KTG);
        run_frag<1, 1>(pAct, pWz, zg, MR, MTS, KTG, 1, nullptr, nullptr, nullptr);
        run_frag<1, 1>(pAct, pWr, rg, MR, MTS, KTG, 1, nullptr, nullptr, nullptr);
        k_packA_f<2><<<dim3(KTG, MTS), 256>>>(rg, nfIn, agg, pAct, KTG);
        run_frag<3, 1>(pAct, pWt, nfOut, MR, MTS, KTG, 1, nullptr, zg, nfIn);

        nfIn = nfOut;
    }
}

// round 16
// speedup vs baseline: 1.3076x; 1.2684x over previous
#include <cuda_runtime.h>
#include <cstdint>
#include <math.h>

// ---------------- problem constants ----------------
#define BB 8
#define NN 1000
#define EE 4000
#define HH 256

// GEMM tiling: CTA tile 128x64 (grid.x=4), k-tile 16.
#define MT12 32      // GEMM1/2: M=4000 -> 32 tiles of 128
#define KT12 63      // K=1000  -> 63 tiles of 16
#define MT34 8       // GEMM3/4: M=1000 -> 8 tiles
#define KT34 250     // K=4000  -> 250 tiles (EE=4000 exactly)

// small-GEMM tiling
#define MTS 63
#define KTF 64
#define KTG 32

#define PA12_SZ (MT12*KT12*4096*BB)
#define PA34_SZ (MT34*KT34*4096*BB)
#define PB_NF_SZ (KT12*2*4096*BB)
#define PB_T_SZ  (KT34*2*4096*BB)
#define PACT_SZ  (MTS*KTF*4096)

// ---------------- scratch (static device globals; no allocation) ----------------
__device__ float g_pA1[PA12_SZ];
__device__ float g_pA2[PA12_SZ];
__device__ float g_pA3[PA34_SZ];
__device__ float g_pA4[PA34_SZ];
__device__ float g_pBnf[PB_NF_SZ];
__device__ float g_pBt1[PB_T_SZ];
__device__ float g_pBt2[PB_T_SZ];
__device__ float g_pAct[PACT_SZ];
__device__ float g_pWf[KTF*2*4096];
__device__ float g_pWz[KTG*2*4096];
__device__ float g_pWr[KTG*2*4096];
__device__ float g_pWt[KTG*2*4096];

__device__ float g_bw  [BB*NN*HH];
__device__ float g_fw  [BB*NN*HH];
__device__ float g_agg [BB*NN*HH];
__device__ float g_zg  [BB*NN*HH];
__device__ float g_rg  [BB*NN*HH];
__device__ float g_nf1 [BB*NN*HH];
__device__ float g_WfT [4*HH*HH];
__device__ float g_WzT [2*HH*HH];
__device__ float g_WrT [2*HH*HH];
__device__ float g_WtT [2*HH*HH];

// ---------------- helpers ----------------
__device__ __forceinline__ uint32_t f2tf(float f) {
    uint32_t u; asm("cvt.rna.tf32.f32 %0, %1;" : "=r"(u) : "f"(f)); return u;
}

__device__ __forceinline__ void split2(float x, float& h, float& l) {
    uint32_t hu = f2tf(x);
    h = __uint_as_float(hu);
    float r1 = __fadd_rn(x, -h);
    uint32_t lu = f2tf(r1);
    l = __uint_as_float(lu);
}

__device__ __forceinline__ void mma8(float* d, const uint32_t* a, uint32_t b0, uint32_t b1) {
    asm volatile(
        "mma.sync.aligned.m16n8k8.row.col.f32.tf32.tf32.f32 "
        "{%0,%1,%2,%3},{%4,%5,%6,%7},{%8,%9},{%0,%1,%2,%3};"
        : "+f"(d[0]), "+f"(d[1]), "+f"(d[2]), "+f"(d[3])
        : "r"(a[0]), "r"(a[1]), "r"(a[2]), "r"(a[3]), "r"(b0), "r"(b1));
}

__device__ __forceinline__ void cp_async16(float4* smem_ptr, const float4* gptr) {
    uint32_t s = (uint32_t)__cvta_generic_to_shared(smem_ptr);
    asm volatile("cp.async.cg.shared.global [%0], [%1], 16;" :: "r"(s), "l"(gptr));
}
__device__ __forceinline__ void cp_commit() {
    asm volatile("cp.async.commit_group;");
}
template<int N>
__device__ __forceinline__ void cp_wait() {
    asm volatile("cp.async.wait_group %0;" :: "n"(N));
}

__device__ __forceinline__ int a_frag_off(int mRel, int kRel) {
    int ms = mRel >> 4;
    int ks2 = kRel >> 3;
    int lane = (mRel & 7) * 4 + (kRel & 3);
    int areg = ((kRel >> 2) & 1) * 2 + ((mRel >> 3) & 1);
    return (((ms * 2) + ks2) * 32 + lane) * 4 + areg;
}
__device__ __forceinline__ int b_frag_off(int kRel, int nRel) {
    int ns = nRel >> 3;
    int lane = (nRel & 7) * 4 + (kRel & 3);
    int breg = ((kRel >> 3) & 1) * 2 + ((kRel >> 2) & 1);
    return (ns * 32 + lane) * 4 + breg;
}

// ---------------- pack kernels (R12 versions, vectorized loads) ----------------
template<int TRANSA>
__global__ void __launch_bounds__(256)
k_packA(const float* __restrict__ src, float* __restrict__ dst,
        int M, int K, int lda, long long sSrc, int MT, int KT)
{
    __shared__ float img[4096];
    int kt = blockIdx.x, mt = blockIdx.y, b = blockIdx.z;
    const float* S = src + (long long)b * sSrc;
    int m0 = mt * 128, k0 = kt * 16;
    int tid = threadIdx.x;
#pragma unroll
    for (int it = 0; it < 2; it++) {
        int linear = tid + it * 256;
        float4 v = make_float4(0.f, 0.f, 0.f, 0.f);
        int mR[4], kR[4];
        if (TRANSA == 0) {
            int row = linear >> 2, c4 = (linear & 3) << 2;
            int gm = m0 + row, gk = k0 + c4;
            if (gm < M) {
                if (gk + 3 < K) v = *reinterpret_cast<const float4*>(S + (size_t)gm * lda + gk);
                else {
                    float* p = &v.x;
#pragma unroll
                    for (int j = 0; j < 4; j++) if (gk + j < K) p[j] = S[(size_t)gm * lda + gk + j];
                }
            }
#pragma unroll
            for (int j = 0; j < 4; j++) { mR[j] = row; kR[j] = c4 + j; }
        } else {
            int kk = linear >> 5, m4 = (linear & 31) << 2;
            int gk = k0 + kk, gm = m0 + m4;
            if (gk < K) {
                if (gm + 3 < M) v = *reinterpret_cast<const float4*>(S + (size_t)gk * lda + gm);
                else {
                    float* p = &v.x;
#pragma unroll
                    for (int j = 0; j < 4; j++) if (gm + j < M) p[j] = S[(size_t)gk * lda + gm + j];
                }
            }
#pragma unroll
            for (int j = 0; j < 4; j++) { mR[j] = m4 + j; kR[j] = kk; }
        }
        const float* pv = &v.x;
#pragma unroll
        for (int j = 0; j < 4; j++) {
            float h, l;
            split2(pv[j], h, l);
            int off = a_frag_off(mR[j], kR[j]);
            img[off] = h; img[2048 + off] = l;
        }
    }
    __syncthreads();
    float4* D = reinterpret_cast<float4*>(dst + (((long long)b * MT + mt) * KT + kt) * 4096);
    const float4* I = reinterpret_cast<const float4*>(img);
#pragma unroll
    for (int i = 0; i < 4; i++) D[tid + i * 256] = I[tid + i * 256];
}

// Fused activation A-pack (bit-identical values to build+pack)
template<int SRC>
__global__ void __launch_bounds__(256)
k_packA_f(const float* __restrict__ s1, const float* __restrict__ s2, const float* __restrict__ s3,
          float* __restrict__ dst, int KT)
{
    __shared__ float img[4096];
    int kt = blockIdx.x, mt = blockIdx.y;
    int m0 = mt * 128, k0 = kt * 16;
    int tid = threadIdx.x;
#pragma unroll
    for (int it = 0; it < 2; it++) {
        int linear = tid + it * 256;
        int row = linear >> 2, c4 = (linear & 3) << 2;
        int gm = m0 + row;
#pragma unroll
        for (int j = 0; j < 4; j++) {
            int gk = k0 + c4 + j;
            float val = 0.f;
            if (gm < BB * NN) {
                if (SRC == 0) {
                    int feat = gk >> 8, hcol = gk & 255;
                    float f = s1[(size_t)gm * 256 + hcol];
                    float b = s2[(size_t)gm * 256 + hcol];
                    val = (feat == 0) ? f : (feat == 1) ? b : (feat == 2) ? f * b : f - b;
                } else if (SRC == 1) {
                    val = (gk < 256) ? s1[(size_t)gm * 256 + gk]
                                     : s2[(size_t)gm * 256 + (gk - 256)];
                } else {
                    val = (gk < 256) ? s1[(size_t)gm * 256 + gk] * s2[(size_t)gm * 256 + gk]
                                     : s3[(size_t)gm * 256 + (gk - 256)];
                }
            }
            float h, l;
            split2(val, h, l);
            int off = a_frag_off(row, c4 + j);
            img[off] = h; img[2048 + off] = l;
        }
    }
    __syncthreads();
    float4* D = reinterpret_cast<float4*>(dst + ((long long)mt * KT + kt) * 4096);
    const float4* I = reinterpret_cast<const float4*>(img);
#pragma unroll
    for (int i = 0; i < 4; i++) D[tid + i * 256] = I[tid + i * 256];
}

__global__ void __launch_bounds__(256)
k_packB(const float* __restrict__ src, float* __restrict__ dst, int K, int KT)
{
    __shared__ float img[4096];
    int kt = blockIdx.x, nt = blockIdx.y, b = blockIdx.z;
    const float* S = src + (long long)b * K * 256;
    int k0 = kt * 16, n0 = nt * 128;
    int tid = threadIdx.x;
#pragma unroll
    for (int it = 0; it < 2; it++) {
        int linear = tid + it * 256;
        int kr = linear >> 5, n4 = (linear & 31) << 2;
        int gk = k0 + kr;
        float4 v = make_float4(0.f, 0.f, 0.f, 0.f);
        if (gk < K) v = *reinterpret_cast<const float4*>(S + (size_t)gk * 256 + n0 + n4);
        const float* pv = &v.x;
#pragma unroll
        for (int j = 0; j < 4; j++) {
            float h, l;
            split2(pv[j], h, l);
            int off = b_frag_off(kr, n4 + j);
            img[off] = h; img[2048 + off] = l;
        }
    }
    __syncthreads();
    float4* D = reinterpret_cast<float4*>(dst + (((long long)b * KT + kt) * 2 + nt) * 4096);
    const float4* I = reinterpret_cast<const float4*>(img);
#pragma unroll
    for (int i = 0; i < 4; i++) D[tid + i * 256] = I[tid + i * 256];
}

// ---------------- fragment GEMM: 128x64 CTA tile, 2 CTAs/SM, 4-stage ring ----------------
// MODE: 1=sigmoid, 2=gated fusion (bias, aux1=fw, aux2=bw), 3=GRU out (aux1=z, aux2=h_old),
//       4=store as B-fragment image (C = image base; KTD = dest image k-tile count)
// FOLD: fold fresh accumulator into master every FOLD k-tiles (FOLD=1 precision-critical
// for fusion/GRU GEMMs — R6 regression)
#define STAGES_T 4
#define STAGE_FLOATS 6144
#define FRAG_SMEM (STAGES_T*STAGE_FLOATS*4)   // 98304 bytes

template<int MODE, int FOLD>
__global__ void __launch_bounds__(256, 2)
gemm_frag(const float* __restrict__ pA, const float* __restrict__ pB, float* __restrict__ C,
          int M, int MT, int KT, int KTD,
          const float* __restrict__ bias,
          const float* __restrict__ aux1, const float* __restrict__ aux2)
{
    extern __shared__ float sm[];
    const int tid = threadIdx.x;
    const int nt4 = blockIdx.x, mt = blockIdx.y, b = blockIdx.z;
    const int nt2 = nt4 >> 1, half = nt4 & 1;
    const float4* Abase = reinterpret_cast<const float4*>(pA) + ((long long)b * MT + mt) * KT * 1024;
    const float4* Bbase = reinterpret_cast<const float4*>(pB) + (long long)b * KT * 2048;

    const int lane = tid & 31, warp = tid >> 5;
    const int wm = warp >> 2, wn = warp & 3;
    const int gid = lane >> 2, tig = lane & 3;

    float acc[32], mst[32];
#pragma unroll
    for (int i = 0; i < 32; i++) { acc[i] = 0.f; mst[i] = 0.f; }

    auto issue = [&](int kt) {
        float4* s = reinterpret_cast<float4*>(sm + (kt % STAGES_T) * STAGE_FLOATS);
        const float4* A = Abase + (size_t)kt * 1024;
        const float4* Bt = Bbase + ((size_t)kt * 2 + nt2) * 1024;
#pragma unroll
        for (int i = 0; i < 4; i++) cp_async16(s + tid + i * 256, A + tid + i * 256);
        cp_async16(s + 1024 + tid, Bt + half * 256 + tid);
        cp_async16(s + 1280 + tid, Bt + 512 + half * 256 + tid);
    };
    auto issueG = [&](int g) {
        int kt0 = g * 2;
        if (kt0 < KT) issue(kt0);
        if (kt0 + 1 < KT) issue(kt0 + 1);
    };

    auto compute = [&](int stage) {
        const float* sA = sm + stage * STAGE_FLOATS;
        const float* sB = sm + stage * STAGE_FLOATS + 4096;
        float4 bh[2], bl[2];
#pragma unroll
        for (int ni = 0; ni < 2; ni++) {
            int nsl = wn * 2 + ni;
            bh[ni] = *reinterpret_cast<const float4*>(sB + (nsl * 32 + lane) * 4);
            bl[ni] = *reinterpret_cast<const float4*>(sB + 1024 + (nsl * 32 + lane) * 4);
        }
#pragma unroll
        for (int ks = 0; ks < 2; ks++) {
#pragma unroll
            for (int mi = 0; mi < 4; mi++) {
                int ms = wm * 4 + mi;
                float4 a4h = *reinterpret_cast<const float4*>(sA + ((ms * 2 + ks) * 32 + lane) * 4);
                float4 a4l = *reinterpret_cast<const float4*>(sA + 2048 + ((ms * 2 + ks) * 32 + lane) * 4);
                uint32_t ah[4] = {__float_as_uint(a4h.x), __float_as_uint(a4h.y),
                                  __float_as_uint(a4h.z), __float_as_uint(a4h.w)};
                uint32_t al[4] = {__float_as_uint(a4l.x), __float_as_uint(a4l.y),
                                  __float_as_uint(a4l.z), __float_as_uint(a4l.w)};
#pragma unroll
                for (int ni = 0; ni < 2; ni++) {
                    float* a4 = &acc[(mi * 2 + ni) * 4];
                    uint32_t bhk0 = (ks == 0) ? __float_as_uint(bh[ni].x) : __float_as_uint(bh[ni].z);
                    uint32_t bhk1 = (ks == 0) ? __float_as_uint(bh[ni].y) : __float_as_uint(bh[ni].w);
                    uint32_t blk0 = (ks == 0) ? __float_as_uint(bl[ni].x) : __float_as_uint(bl[ni].z);
                    uint32_t blk1 = (ks == 0) ? __float_as_uint(bl[ni].y) : __float_as_uint(bl[ni].w);
                    mma8(a4, al, bhk0, bhk1);
                    mma8(a4, ah, blk0, blk1);
                    mma8(a4, ah, bhk0, bhk1);
                }
            }
        }
    };

    auto fold = [&]() {
#pragma unroll
        for (int i = 0; i < 32; i++) { mst[i] = __fadd_rn(mst[i], acc[i]); acc[i] = 0.f; }
    };

    const int NG = (KT + 1) >> 1;
    issueG(0); cp_commit();
    issueG(1); cp_commit();

    for (int g = 0; g < NG; g++) {
        cp_wait<1>();
        __syncthreads();
        int kt = g * 2;
        compute(kt % STAGES_T);
        if (((kt + 1) % FOLD) == 0 || kt == KT - 1) fold();
        if (kt + 1 < KT) {
            compute((kt + 1) % STAGES_T);
            if (((kt + 2) % FOLD) == 0 || kt + 1 == KT - 1) fold();
        }
        __syncthreads();
        issueG(g + 2);
        cp_commit();
    }

#pragma unroll
    for (int mi = 0; mi < 4; mi++) {
#pragma unroll
        for (int ni = 0; ni < 2; ni++) {
            int rB = mt * 128 + wm * 64 + mi * 16 + gid;
            int cB = nt4 * 64 + wn * 16 + ni * 8 + tig * 2;
#pragma unroll
            for (int rr = 0; rr < 2; rr++) {
                int r = rB + rr * 8;
                if (r < M) {
#pragma unroll
                    for (int c2 = 0; c2 < 2; c2++) {
                        int c = cB + c2;
                        float v = mst[(mi * 2 + ni) * 4 + rr * 2 + c2];
                        if (MODE == 4) {
                            // write as B-fragment image: identical bits to packB(row-major v)
                            float h, l;
                            split2(v, h, l);
                            int off = b_frag_off(r & 15, c & 127);
                            long long base = (((long long)b * KTD + (r >> 4)) * 2 + (c >> 7)) * 4096;
                            C[base + off] = h;
                            C[base + 2048 + off] = l;
                        } else {
                            size_t idx = (long long)b * M * 256 + (size_t)r * 256 + c;
                            if (MODE == 1) {
                                C[idx] = 1.f / (1.f + expf(-v));
                            } else if (MODE == 2) {
                                float z = 1.f / (1.f + expf(-(v + bias[c])));
                                C[idx] = (1.f - z) * aux1[idx] + z * aux2[idx];
                            } else {
                                float t = tanhf(v);
                                float z = aux1[idx];
                                C[idx] = (1.f - z) * aux2[idx] + z * t;
                            }
                        }
                    }
                }
            }
        }
    }
}

// ---------------- big GEMM 3/4: MODE 0 analogue (row-major store) ----------------
__global__ void __launch_bounds__(256, 2)
gemm_frag_store(const float* __restrict__ pA, const float* __restrict__ pB, float* __restrict__ C,
                int M, int MT, int KT)
{
    extern __shared__ float sm[];
    const int tid = threadIdx.x;
    const int nt4 = blockIdx.x, mt = blockIdx.y, b = blockIdx.z;
    const int nt2 = nt4 >> 1, half = nt4 & 1;
    const float4* Abase = reinterpret_cast<const float4*>(pA) + ((long long)b * MT + mt) * KT * 1024;
    const float4* Bbase = reinterpret_cast<const float4*>(pB) + (long long)b * KT * 2048;

    const int lane = tid & 31, warp = tid >> 5;
    const int wm = warp >> 2, wn = warp & 3;
    const int gid = lane >> 2, tig = lane & 3;

    float acc[32], mst[32];
#pragma unroll
    for (int i = 0; i < 32; i++) { acc[i] = 0.f; mst[i] = 0.f; }

    auto issue = [&](int kt) {
        float4* s = reinterpret_cast<float4*>(sm + (kt % STAGES_T) * STAGE_FLOATS);
        const float4* A = Abase + (size_t)kt * 1024;
        const float4* Bt = Bbase + ((size_t)kt * 2 + nt2) * 1024;
#pragma unroll
        for (int i = 0; i < 4; i++) cp_async16(s + tid + i * 256, A + tid + i * 256);
        cp_async16(s + 1024 + tid, Bt + half * 256 + tid);
        cp_async16(s + 1280 + tid, Bt + 512 + half * 256 + tid);
    };
    auto issueG = [&](int g) {
        int kt0 = g * 2;
        if (kt0 < KT) issue(kt0);
        if (kt0 + 1 < KT) issue(kt0 + 1);
    };

    auto compute = [&](int stage) {
        const float* sA = sm + stage * STAGE_FLOATS;
        const float* sB = sm + stage * STAGE_FLOATS + 4096;
        float4 bh[2], bl[2];
#pragma unroll
        for (int ni = 0; ni < 2; ni++) {
            int nsl = wn * 2 + ni;
            bh[ni] = *reinterpret_cast<const float4*>(sB + (nsl * 32 + lane) * 4);
            bl[ni] = *reinterpret_cast<const float4*>(sB + 1024 + (nsl * 32 + lane) * 4);
        }
#pragma unroll
        for (int ks = 0; ks < 2; ks++) {
#pragma unroll
            for (int mi = 0; mi < 4; mi++) {
                int ms = wm * 4 + mi;
                float4 a4h = *reinterpret_cast<const float4*>(sA + ((ms * 2 + ks) * 32 + lane) * 4);
                float4 a4l = *reinterpret_cast<const float4*>(sA + 2048 + ((ms * 2 + ks) * 32 + lane) * 4);
                uint32_t ah[4] = {__float_as_uint(a4h.x), __float_as_uint(a4h.y),
                                  __float_as_uint(a4h.z), __float_as_uint(a4h.w)};
                uint32_t al[4] = {__float_as_uint(a4l.x), __float_as_uint(a4l.y),
                                  __float_as_uint(a4l.z), __float_as_uint(a4l.w)};
#pragma unroll
                for (int ni = 0; ni < 2; ni++) {
                    float* a4 = &acc[(mi * 2 + ni) * 4];
                    uint32_t bhk0 = (ks == 0) ? __float_as_uint(bh[ni].x) : __float_as_uint(bh[ni].z);
                    uint32_t bhk1 = (ks == 0) ? __float_as_uint(bh[ni].y) : __float_as_uint(bh[ni].w);
                    uint32_t blk0 = (ks == 0) ? __float_as_uint(bl[ni].x) : __float_as_uint(bl[ni].z);
                    uint32_t blk1 = (ks == 0) ? __float_as_uint(bl[ni].y) : __float_as_uint(bl[ni].w);
                    mma8(a4, al, bhk0, bhk1);
                    mma8(a4, ah, blk0, blk1);
                    mma8(a4, ah, bhk0, bhk1);
                }
            }
        }
    };

    auto fold = [&]() {
#pragma unroll
        for (int i = 0; i < 32; i++) { mst[i] = __fadd_rn(mst[i], acc[i]); acc[i] = 0.f; }
    };

    const int NG = (KT + 1) >> 1;
    issueG(0); cp_commit();
    issueG(1); cp_commit();

    for (int g = 0; g < NG; g++) {
        cp_wait<1>();
        __syncthreads();
        int kt = g * 2;
        compute(kt % STAGES_T);
        if (((kt + 1) & 3) == 0 || kt == KT - 1) fold();
        if (kt + 1 < KT) {
            compute((kt + 1) % STAGES_T);
            if (((kt + 2) & 3) == 0 || kt + 1 == KT - 1) fold();
        }
        __syncthreads();
        issueG(g + 2);
        cp_commit();
    }

    float* Cb = C + (long long)b * M * 256;
#pragma unroll
    for (int mi = 0; mi < 4; mi++) {
#pragma unroll
        for (int ni = 0; ni < 2; ni++) {
            int rB = mt * 128 + wm * 64 + mi * 16 + gid;
            int cB = nt4 * 64 + wn * 16 + ni * 8 + tig * 2;
#pragma unroll
            for (int rr = 0; rr < 2; rr++) {
                int r = rB + rr * 8;
                if (r < M) {
                    Cb[(size_t)r * 256 + cB]     = mst[(mi * 2 + ni) * 4 + rr * 2 + 0];
                    Cb[(size_t)r * 256 + cB + 1] = mst[(mi * 2 + ni) * 4 + rr * 2 + 1];
                }
            }
        }
    }
}

// ---------------- fused weight transpose ----------------
__global__ void k_transW(const float* __restrict__ Wf, const float* __restrict__ Wz,
                         const float* __restrict__ Wr, const float* __restrict__ Wt,
                         float* __restrict__ WfT, float* __restrict__ WzT,
                         float* __restrict__ WrT, float* __restrict__ WtT)
{
    __shared__ float t[32][33];
    int x = threadIdx.x, y = threadIdx.y;
    const float* srcs[4] = {Wf, Wz, Wr, Wt};
    float* dsts[4] = {WfT, WzT, WrT, WtT};
    const int Cs[4] = {1024, 512, 512, 512};
#pragma unroll
    for (int w = 0; w < 4; w++) {
        int C = Cs[w];
        const int R = 256;
        if (blockIdx.x * 32 >= C) continue;
        int bx = blockIdx.x * 32, by = blockIdx.y * 32;
        __syncthreads();
#pragma unroll
        for (int j = 0; j < 32; j += 8) {
            int r = by + y + j, c = bx + x;
            t[y + j][x] = srcs[w][(size_t)r * C + c];
        }
        __syncthreads();
#pragma unroll
        for (int j = 0; j < 32; j += 8) {
            int r = bx + y + j, c = by + x;
            dsts[w][(size_t)r * R + c] = t[x][y + j];
        }
    }
}

// ---------------- host side ----------------
template<int MODE, int FOLD>
static void run_frag(const float* pA, const float* pB, float* C, int M, int MT, int KT, int KTD,
                     int batch, const float* bias, const float* a1, const float* a2)
{
    cudaFuncSetAttribute(gemm_frag<MODE, FOLD>, cudaFuncAttributeMaxDynamicSharedMemorySize, FRAG_SMEM);
    dim3 grid(4, MT, batch);
    gemm_frag<MODE, FOLD><<<grid, 256, FRAG_SMEM>>>(pA, pB, C, M, MT, KT, KTD, bias, a1, a2);
}

static void run_store(const float* pA, const float* pB, float* C, int M, int MT, int KT)
{
    cudaFuncSetAttribute(gemm_frag_store, cudaFuncAttributeMaxDynamicSharedMemorySize, FRAG_SMEM);
    dim3 grid(4, MT, BB);
    gemm_frag_store<<<grid, 256, FRAG_SMEM>>>(pA, pB, C, M, MT, KT);
}

extern "C" void kernel_launch(void* const* d_in, const int* in_sizes, int n_in,
                              void* d_out, int out_size)
{
    const float* node_feature = (const float*)d_in[0];
    const float* node2edge    = (const float*)d_in[1];
    const float* edge2node    = (const float*)d_in[2];
    const float* Wz = (const float*)d_in[3];
    const float* Wr = (const float*)d_in[4];
    const float* Wt = (const float*)d_in[5];
    const float* Wf = (const float*)d_in[6];
    const float* bf = (const float*)d_in[7];
    float* out = (float*)d_out;

    float *pA1, *pA2, *pA3, *pA4, *pBnf, *pBt1, *pBt2, *pAct, *pWf, *pWz, *pWr, *pWt;
    float *bwP, *fwP, *agg, *zg, *rg, *nf1;
    float *WfT, *WzT, *WrT, *WtT;
    cudaGetSymbolAddress((void**)&pA1, g_pA1);
    cudaGetSymbolAddress((void**)&pA2, g_pA2);
    cudaGetSymbolAddress((void**)&pA3, g_pA3);
    cudaGetSymbolAddress((void**)&pA4, g_pA4);
    cudaGetSymbolAddress((void**)&pBnf, g_pBnf);
    cudaGetSymbolAddress((void**)&pBt1, g_pBt1);
    cudaGetSymbolAddress((void**)&pBt2, g_pBt2);
    cudaGetSymbolAddress((void**)&pAct, g_pAct);
    cudaGetSymbolAddress((void**)&pWf, g_pWf);
    cudaGetSymbolAddress((void**)&pWz, g_pWz);
    cudaGetSymbolAddress((void**)&pWr, g_pWr);
    cudaGetSymbolAddress((void**)&pWt, g_pWt);
    cudaGetSymbolAddress((void**)&bwP,  g_bw);
    cudaGetSymbolAddress((void**)&fwP,  g_fw);
    cudaGetSymbolAddress((void**)&agg,  g_agg);
    cudaGetSymbolAddress((void**)&zg,   g_zg);
    cudaGetSymbolAddress((void**)&rg,   g_rg);
    cudaGetSymbolAddress((void**)&nf1,  g_nf1);
    cudaGetSymbolAddress((void**)&WfT,  g_WfT);
    cudaGetSymbolAddress((void**)&WzT,  g_WzT);
    cudaGetSymbolAddress((void**)&WrT,  g_WrT);
    cudaGetSymbolAddress((void**)&WtT,  g_WtT);

    // weights: one fused transpose launch, then B-images
    k_transW<<<dim3(32, 8), dim3(32, 8)>>>(Wf, Wz, Wr, Wt, WfT, WzT, WrT, WtT);
    k_packB<<<dim3(KTF, 2, 1), 256>>>(WfT, pWf, 4 * HH, KTF);
    k_packB<<<dim3(KTG, 2, 1), 256>>>(WzT, pWz, 2 * HH, KTG);
    k_packB<<<dim3(KTG, 2, 1), 256>>>(WrT, pWr, 2 * HH, KTG);
    k_packB<<<dim3(KTG, 2, 1), 256>>>(WtT, pWt, 2 * HH, KTG);

    const long long sPQ = (long long)EE * NN;
    const int MR = BB * NN;   // 8000

    // pack adjacency fragment images (reused both hops)
    k_packA<0><<<dim3(KT12, MT12, BB), 256>>>(node2edge, pA1, EE, NN, NN, sPQ, MT12, KT12);
    k_packA<1><<<dim3(KT12, MT12, BB), 256>>>(edge2node, pA2, EE, NN, EE, sPQ, MT12, KT12);
    k_packA<0><<<dim3(KT34, MT34, BB), 256>>>(edge2node, pA3, NN, EE, EE, sPQ, MT34, KT34);
    k_packA<1><<<dim3(KT34, MT34, BB), 256>>>(node2edge, pA4, NN, EE, NN, sPQ, MT34, KT34);

    const float* nfIn = node_feature;
    for (int hop = 0; hop < 2; hop++) {
        float* nfOut = (hop == 1) ? out : nf1;

        // pack nf as B image
        k_packB<<<dim3(KT12, 2, BB), 256>>>(nfIn, pBnf, NN, KT12);

        // tmp1/tmp2 GEMMs write DIRECTLY as B-fragment images (MODE 4):
        // identical bits to row-major store + packB round trip, minus a full pass.
        run_frag<4, 4>(pA1, pBnf, pBt1, EE, MT12, KT12, KT34, BB, nullptr, nullptr, nullptr);
        run_frag<4, 4>(pA2, pBnf, pBt2, EE, MT12, KT12, KT34, BB, nullptr, nullptr, nullptr);

        // bw = edge2node @ tmp1 ; fw = node2edge^T @ tmp2
        run_store(pA3, pBt1, bwP, NN, MT34, KT34);
        run_store(pA4, pBt2, fwP, NN, MT34, KT34);

        // gated fusion
        k_packA_f<0><<<dim3(KTF, MTS), 256>>>(fwP, bwP, nullptr, pAct, KTF);
        run_frag<2, 1>(pAct, pWf, agg, MR, MTS, KTF, 0, 1, bf, fwP, bwP);

        // GRU step
        k_packA_f<1><<<dim3(KTG, MTS), 256>>>(nfIn, agg, nullptr, pAct, KTG);
        run_frag<1, 1>(pAct, pWz, zg, MR, MTS, KTG, 0, 1, nullptr, nullptr, nullptr);
        run_frag<1, 1>(pAct, pWr, rg, MR, MTS, KTG, 0, 1, nullptr, nullptr, nullptr);
        k_packA_f<2><<<dim3(KTG, MTS), 256>>>(rg, nfIn, agg, pAct, KTG);
        run_frag<3, 1>(pAct, pWt, nfOut, MR, MTS, KTG, 0, 1, nullptr, zg, nfIn);

        nfIn = nfOut;
    }
}

// round 17
// speedup vs baseline: 1.3259x; 1.0140x over previous
#include <cuda_runtime.h>
#include <cstdint>
#include <math.h>

// ---------------- problem constants ----------------
#define BB 8
#define NN 1000
#define EE 4000
#define HH 256

#define MT12 32      // GEMM1/2: M=4000 -> 32 tiles of 128
#define KT12 63      // K=1000  -> 63 tiles of 16
#define MT34 8       // GEMM3/4: M=1000 -> 8 tiles
#define KT34 250     // K=4000  -> 250 tiles

#define MTS 63
#define KTF 64
#define KTG 32

#define PA12_SZ (MT12*KT12*4096*BB)
#define PA34_SZ (MT34*KT34*4096*BB)
#define PB_NF_SZ (KT12*2*4096*BB)
#define PB_T_SZ  (KT34*2*4096*BB)
#define PACT_SZ  (MTS*KTF*4096)
#define PACT2_SZ (MTS*KTG*4096)

// ---------------- scratch (static device globals; no allocation) ----------------
__device__ float g_pA1[PA12_SZ];
__device__ float g_pA2[PA12_SZ];
__device__ float g_pA3[PA34_SZ];
__device__ float g_pA4[PA34_SZ];
__device__ float g_pBnf[PB_NF_SZ];
__device__ float g_pBt1[PB_T_SZ];
__device__ float g_pBt2[PB_T_SZ];
__device__ float g_pAct[PACT_SZ];    // cat4 A-image (KTF layout)
__device__ float g_pAct2[PACT2_SZ];  // hx / cat2 A-image (KTG layout)
__device__ float g_pWf[KTF*2*4096];
__device__ float g_pWz[KTG*2*4096];
__device__ float g_pWr[KTG*2*4096];
__device__ float g_pWt[KTG*2*4096];

__device__ float g_bw  [BB*NN*HH];
__device__ float g_fw  [BB*NN*HH];
__device__ float g_zg  [BB*NN*HH];
__device__ float g_rg  [BB*NN*HH];
__device__ float g_nf1 [BB*NN*HH];
__device__ float g_WfT [4*HH*HH];
__device__ float g_WzT [2*HH*HH];
__device__ float g_WrT [2*HH*HH];
__device__ float g_WtT [2*HH*HH];

// ---------------- helpers ----------------
__device__ __forceinline__ uint32_t f2tf(float f) {
    uint32_t u; asm("cvt.rna.tf32.f32 %0, %1;" : "=r"(u) : "f"(f)); return u;
}

__device__ __forceinline__ void split2(float x, float& h, float& l) {
    uint32_t hu = f2tf(x);
    h = __uint_as_float(hu);
    float r1 = __fadd_rn(x, -h);
    uint32_t lu = f2tf(r1);
    l = __uint_as_float(lu);
}

__device__ __forceinline__ void mma8(float* d, const uint32_t* a, uint32_t b0, uint32_t b1) {
    asm volatile(
        "mma.sync.aligned.m16n8k8.row.col.f32.tf32.tf32.f32 "
        "{%0,%1,%2,%3},{%4,%5,%6,%7},{%8,%9},{%0,%1,%2,%3};"
        : "+f"(d[0]), "+f"(d[1]), "+f"(d[2]), "+f"(d[3])
        : "r"(a[0]), "r"(a[1]), "r"(a[2]), "r"(a[3]), "r"(b0), "r"(b1));
}

__device__ __forceinline__ void cp_async16(float4* smem_ptr, const float4* gptr) {
    uint32_t s = (uint32_t)__cvta_generic_to_shared(smem_ptr);
    asm volatile("cp.async.cg.shared.global [%0], [%1], 16;" :: "r"(s), "l"(gptr));
}
__device__ __forceinline__ void cp_commit() {
    asm volatile("cp.async.commit_group;");
}
template<int N>
__device__ __forceinline__ void cp_wait() {
    asm volatile("cp.async.wait_group %0;" :: "n"(N));
}

__device__ __forceinline__ int a_frag_off(int mRel, int kRel) {
    int ms = mRel >> 4;
    int ks2 = kRel >> 3;
    int lane = (mRel & 7) * 4 + (kRel & 3);
    int areg = ((kRel >> 2) & 1) * 2 + ((mRel >> 3) & 1);
    return (((ms * 2) + ks2) * 32 + lane) * 4 + areg;
}
__device__ __forceinline__ int b_frag_off(int kRel, int nRel) {
    int ns = nRel >> 3;
    int lane = (nRel & 7) * 4 + (kRel & 3);
    int breg = ((kRel >> 3) & 1) * 2 + ((kRel >> 2) & 1);
    return (ns * 32 + lane) * 4 + breg;
}

// ---------------- pack kernels ----------------
template<int TRANSA>
__global__ void __launch_bounds__(256)
k_packA(const float* __restrict__ src, float* __restrict__ dst,
        int M, int K, int lda, long long sSrc, int MT, int KT)
{
    __shared__ float img[4096];
    int kt = blockIdx.x, mt = blockIdx.y, b = blockIdx.z;
    const float* S = src + (long long)b * sSrc;
    int m0 = mt * 128, k0 = kt * 16;
    int tid = threadIdx.x;
#pragma unroll
    for (int it = 0; it < 2; it++) {
        int linear = tid + it * 256;
        float4 v = make_float4(0.f, 0.f, 0.f, 0.f);
        int mR[4], kR[4];
        if (TRANSA == 0) {
            int row = linear >> 2, c4 = (linear & 3) << 2;
            int gm = m0 + row, gk = k0 + c4;
            if (gm < M) {
                if (gk + 3 < K) v = *reinterpret_cast<const float4*>(S + (size_t)gm * lda + gk);
                else {
                    float* p = &v.x;
#pragma unroll
                    for (int j = 0; j < 4; j++) if (gk + j < K) p[j] = S[(size_t)gm * lda + gk + j];
                }
            }
#pragma unroll
            for (int j = 0; j < 4; j++) { mR[j] = row; kR[j] = c4 + j; }
        } else {
            int kk = linear >> 5, m4 = (linear & 31) << 2;
            int gk = k0 + kk, gm = m0 + m4;
            if (gk < K) {
                if (gm + 3 < M) v = *reinterpret_cast<const float4*>(S + (size_t)gk * lda + gm);
                else {
                    float* p = &v.x;
#pragma unroll
                    for (int j = 0; j < 4; j++) if (gm + j < M) p[j] = S[(size_t)gk * lda + gm + j];
                }
            }
#pragma unroll
            for (int j = 0; j < 4; j++) { mR[j] = m4 + j; kR[j] = kk; }
        }
        const float* pv = &v.x;
#pragma unroll
        for (int j = 0; j < 4; j++) {
            float h, l;
            split2(pv[j], h, l);
            int off = a_frag_off(mR[j], kR[j]);
            img[off] = h; img[2048 + off] = l;
        }
    }
    __syncthreads();
    float4* D = reinterpret_cast<float4*>(dst + (((long long)b * MT + mt) * KT + kt) * 4096);
    const float4* I = reinterpret_cast<const float4*>(img);
#pragma unroll
    for (int i = 0; i < 4; i++) D[tid + i * 256] = I[tid + i * 256];
}

// Fused activation A-pack, restricted tile range [ktOff, ktOff+gridDim.x).
// SRC 0: cat4 product features (gk>=512): fw*bw, fw-bw  (s1=fw, s2=bw)
// SRC 1: nf half (gk<256): s1=nf
// SRC 2: rg*nf half (gk<256): s1=rg, s2=nf
template<int SRC>
__global__ void __launch_bounds__(256)
k_packA_f(const float* __restrict__ s1, const float* __restrict__ s2,
          float* __restrict__ dst, int KTdest, int ktOff)
{
    __shared__ float img[4096];
    int kt = blockIdx.x + ktOff, mt = blockIdx.y;
    int m0 = mt * 128, k0 = kt * 16;
    int tid = threadIdx.x;
#pragma unroll
    for (int it = 0; it < 2; it++) {
        int linear = tid + it * 256;
        int row = linear >> 2, c4 = (linear & 3) << 2;
        int gm = m0 + row;
#pragma unroll
        for (int j = 0; j < 4; j++) {
            int gk = k0 + c4 + j;
            float val = 0.f;
            if (gm < BB * NN) {
                if (SRC == 0) {
                    int feat = gk >> 8, hcol = gk & 255;
                    float f = s1[(size_t)gm * 256 + hcol];
                    float b = s2[(size_t)gm * 256 + hcol];
                    val = (feat == 2) ? f * b : f - b;
                } else if (SRC == 1) {
                    val = s1[(size_t)gm * 256 + gk];
                } else {
                    val = s1[(size_t)gm * 256 + gk] * s2[(size_t)gm * 256 + gk];
                }
            }
            float h, l;
            split2(val, h, l);
            int off = a_frag_off(row, c4 + j);
            img[off] = h; img[2048 + off] = l;
        }
    }
    __syncthreads();
    float4* D = reinterpret_cast<float4*>(dst + ((long long)mt * KTdest + kt) * 4096);
    const float4* I = reinterpret_cast<const float4*>(img);
#pragma unroll
    for (int i = 0; i < 4; i++) D[tid + i * 256] = I[tid + i * 256];
}

__global__ void __launch_bounds__(256)
k_packB(const float* __restrict__ src, float* __restrict__ dst, int K, int KT)
{
    __shared__ float img[4096];
    int kt = blockIdx.x, nt = blockIdx.y, b = blockIdx.z;
    const float* S = src + (long long)b * K * 256;
    int k0 = kt * 16, n0 = nt * 128;
    int tid = threadIdx.x;
#pragma unroll
    for (int it = 0; it < 2; it++) {
        int linear = tid + it * 256;
        int kr = linear >> 5, n4 = (linear & 31) << 2;
        int gk = k0 + kr;
        float4 v = make_float4(0.f, 0.f, 0.f, 0.f);
        if (gk < K) v = *reinterpret_cast<const float4*>(S + (size_t)gk * 256 + n0 + n4);
        const float* pv = &v.x;
#pragma unroll
        for (int j = 0; j < 4; j++) {
            float h, l;
            split2(pv[j], h, l);
            int off = b_frag_off(kr, n4 + j);
            img[off] = h; img[2048 + off] = l;
        }
    }
    __syncthreads();
    float4* D = reinterpret_cast<float4*>(dst + (((long long)b * KT + kt) * 2 + nt) * 4096);
    const float4* I = reinterpret_cast<const float4*>(img);
#pragma unroll
    for (int i = 0; i < 4; i++) D[tid + i * 256] = I[tid + i * 256];
}

// ---------------- fragment GEMM: 128x64 CTA tile, 2 CTAs/SM, 4-stage ring ----------------
// MODE 1: sigmoid -> C row-major [M,256], batch folded in M
// MODE 2: gated fusion -> writes agg DIRECTLY as A-image half (img, KTG layout, tiles 16..31)
// MODE 3: GRU out -> C row-major; if imgOn, ALSO writes nf B-image (img, KTD=KT12 layout)
// MODE 4: writes result as B-fragment image into C (KTD layout)
#define STAGES_T 4
#define STAGE_FLOATS 6144
#define FRAG_SMEM (STAGES_T*STAGE_FLOATS*4)   // 98304 bytes

template<int MODE, int FOLD>
__global__ void __launch_bounds__(256, 2)
gemm_frag(const float* __restrict__ pA, const float* __restrict__ pB, float* __restrict__ C,
          int M, int MT, int KT, int KTD,
          const float* __restrict__ bias,
          const float* __restrict__ aux1, const float* __restrict__ aux2,
          float* __restrict__ img, int imgOn)
{
    extern __shared__ float sm[];
    const int tid = threadIdx.x;
    const int nt4 = blockIdx.x, mt = blockIdx.y, b = blockIdx.z;
    const int nt2 = nt4 >> 1, half = nt4 & 1;
    const float4* Abase = reinterpret_cast<const float4*>(pA) + ((long long)b * MT + mt) * KT * 1024;
    const float4* Bbase = reinterpret_cast<const float4*>(pB) + (long long)b * KT * 2048;

    const int lane = tid & 31, warp = tid >> 5;
    const int wm = warp >> 2, wn = warp & 3;
    const int gid = lane >> 2, tig = lane & 3;

    float acc[32], mst[32];
#pragma unroll
    for (int i = 0; i < 32; i++) { acc[i] = 0.f; mst[i] = 0.f; }

    auto issue = [&](int kt) {
        float4* s = reinterpret_cast<float4*>(sm + (kt % STAGES_T) * STAGE_FLOATS);
        const float4* A = Abase + (size_t)kt * 1024;
        const float4* Bt = Bbase + ((size_t)kt * 2 + nt2) * 1024;
#pragma unroll
        for (int i = 0; i < 4; i++) cp_async16(s + tid + i * 256, A + tid + i * 256);
        cp_async16(s + 1024 + tid, Bt + half * 256 + tid);
        cp_async16(s + 1280 + tid, Bt + 512 + half * 256 + tid);
    };
    auto issueG = [&](int g) {
        int kt0 = g * 2;
        if (kt0 < KT) issue(kt0);
        if (kt0 + 1 < KT) issue(kt0 + 1);
    };

    auto compute = [&](int stage) {
        const float* sA = sm + stage * STAGE_FLOATS;
        const float* sB = sm + stage * STAGE_FLOATS + 4096;
        float4 bh[2], bl[2];
#pragma unroll
        for (int ni = 0; ni < 2; ni++) {
            int nsl = wn * 2 + ni;
            bh[ni] = *reinterpret_cast<const float4*>(sB + (nsl * 32 + lane) * 4);
            bl[ni] = *reinterpret_cast<const float4*>(sB + 1024 + (nsl * 32 + lane) * 4);
        }
#pragma unroll
        for (int ks = 0; ks < 2; ks++) {
#pragma unroll
            for (int mi = 0; mi < 4; mi++) {
                int ms = wm * 4 + mi;
                float4 a4h = *reinterpret_cast<const float4*>(sA + ((ms * 2 + ks) * 32 + lane) * 4);
                float4 a4l = *reinterpret_cast<const float4*>(sA + 2048 + ((ms * 2 + ks) * 32 + lane) * 4);
                uint32_t ah[4] = {__float_as_uint(a4h.x), __float_as_uint(a4h.y),
                                  __float_as_uint(a4h.z), __float_as_uint(a4h.w)};
                uint32_t al[4] = {__float_as_uint(a4l.x), __float_as_uint(a4l.y),
                                  __float_as_uint(a4l.z), __float_as_uint(a4l.w)};
#pragma unroll
                for (int ni = 0; ni < 2; ni++) {
                    float* a4 = &acc[(mi * 2 + ni) * 4];
                    uint32_t bhk0 = (ks == 0) ? __float_as_uint(bh[ni].x) : __float_as_uint(bh[ni].z);
                    uint32_t bhk1 = (ks == 0) ? __float_as_uint(bh[ni].y) : __float_as_uint(bh[ni].w);
                    uint32_t blk0 = (ks == 0) ? __float_as_uint(bl[ni].x) : __float_as_uint(bl[ni].z);
                    uint32_t blk1 = (ks == 0) ? __float_as_uint(bl[ni].y) : __float_as_uint(bl[ni].w);
                    mma8(a4, al, bhk0, bhk1);
                    mma8(a4, ah, blk0, blk1);
                    mma8(a4, ah, bhk0, bhk1);
                }
            }
        }
    };

    auto fold = [&]() {
#pragma unroll
        for (int i = 0; i < 32; i++) { mst[i] = __fadd_rn(mst[i], acc[i]); acc[i] = 0.f; }
    };

    const int NG = (KT + 1) >> 1;
    issueG(0); cp_commit();
    issueG(1); cp_commit();

    for (int g = 0; g < NG; g++) {
        cp_wait<1>();
        __syncthreads();
        int kt = g * 2;
        compute(kt % STAGES_T);
        if (((kt + 1) % FOLD) == 0 || kt == KT - 1) fold();
        if (kt + 1 < KT) {
            compute((kt + 1) % STAGES_T);
            if (((kt + 2) % FOLD) == 0 || kt + 1 == KT - 1) fold();
        }
        __syncthreads();
        issueG(g + 2);
        cp_commit();
    }

#pragma unroll
    for (int mi = 0; mi < 4; mi++) {
#pragma unroll
        for (int ni = 0; ni < 2; ni++) {
            int rB = mt * 128 + wm * 64 + mi * 16 + gid;
            int cB = nt4 * 64 + wn * 16 + ni * 8 + tig * 2;
#pragma unroll
            for (int rr = 0; rr < 2; rr++) {
                int r = rB + rr * 8;
                if (r < M) {
#pragma unroll
                    for (int c2 = 0; c2 < 2; c2++) {
                        int c = cB + c2;
                        float v = mst[(mi * 2 + ni) * 4 + rr * 2 + c2];
                        if (MODE == 4) {
                            float h, l;
                            split2(v, h, l);
                            int off = b_frag_off(r & 15, c & 127);
                            long long base = (((long long)b * KTD + (r >> 4)) * 2 + (c >> 7)) * 4096;
                            C[base + off] = h;
                            C[base + 2048 + off] = l;
                        } else if (MODE == 2) {
                            size_t idx = (size_t)r * 256 + c;
                            float z = 1.f / (1.f + expf(-(v + bias[c])));
                            float val = (1.f - z) * aux1[idx] + z * aux2[idx];
                            float h, l;
                            split2(val, h, l);
                            int off = a_frag_off(r & 127, c & 15);
                            long long base = ((long long)(r >> 7) * KTG + 16 + (c >> 4)) * 4096;
                            img[base + off] = h;
                            img[base + 2048 + off] = l;
                        } else {
                            size_t idx = (long long)b * M * 256 + (size_t)r * 256 + c;
                            if (MODE == 1) {
                                C[idx] = 1.f / (1.f + expf(-v));
                            } else {   // MODE 3
                                float t = tanhf(v);
                                float z = aux1[idx];
                                float val = (1.f - z) * aux2[idx] + z * t;
                                C[idx] = val;
                                if (imgOn) {
                                    int bi = r / NN;
                                    int n = r - bi * NN;
                                    float h, l;
                                    split2(val, h, l);
                                    int off = b_frag_off(n & 15, c & 127);
                                    long long base = (((long long)bi * KTD + (n >> 4)) * 2 + (c >> 7)) * 4096;
                                    img[base + off] = h;
                                    img[base + 2048 + off] = l;
                                }
                            }
                        }
                    }
                }
            }
        }
    }
}

// ---------------- big GEMM 3/4: row-major store + cat4 A-image dual store ----------------
__global__ void __launch_bounds__(256, 2)
gemm_frag_store(const float* __restrict__ pA, const float* __restrict__ pB, float* __restrict__ C,
                int M, int MT, int KT, float* __restrict__ img, int ktOff)
{
    extern __shared__ float sm[];
    const int tid = threadIdx.x;
    const int nt4 = blockIdx.x, mt = blockIdx.y, b = blockIdx.z;
    const int nt2 = nt4 >> 1, half = nt4 & 1;
    const float4* Abase = reinterpret_cast<const float4*>(pA) + ((long long)b * MT + mt) * KT * 1024;
    const float4* Bbase = reinterpret_cast<const float4*>(pB) + (long long)b * KT * 2048;

    const int lane = tid & 31, warp = tid >> 5;
    const int wm = warp >> 2, wn = warp & 3;
    const int gid = lane >> 2, tig = lane & 3;

    float acc[32], mst[32];
#pragma unroll
    for (int i = 0; i < 32; i++) { acc[i] = 0.f; mst[i] = 0.f; }

    auto issue = [&](int kt) {
        float4* s = reinterpret_cast<float4*>(sm + (kt % STAGES_T) * STAGE_FLOATS);
        const float4* A = Abase + (size_t)kt * 1024;
        const float4* Bt = Bbase + ((size_t)kt * 2 + nt2) * 1024;
#pragma unroll
        for (int i = 0; i < 4; i++) cp_async16(s + tid + i * 256, A + tid + i * 256);
        cp_async16(s + 1024 + tid, Bt + half * 256 + tid);
        cp_async16(s + 1280 + tid, Bt + 512 + half * 256 + tid);
    };
    auto issueG = [&](int g) {
        int kt0 = g * 2;
        if (kt0 < KT) issue(kt0);
        if (kt0 + 1 < KT) issue(kt0 + 1);
    };

    auto compute = [&](int stage) {
        const float* sA = sm + stage * STAGE_FLOATS;
        const float* sB = sm + stage * STAGE_FLOATS + 4096;
        float4 bh[2], bl[2];
#pragma unroll
        for (int ni = 0; ni < 2; ni++) {
            int nsl = wn * 2 + ni;
            bh[ni] = *reinterpret_cast<const float4*>(sB + (nsl * 32 + lane) * 4);
            bl[ni] = *reinterpret_cast<const float4*>(sB + 1024 + (nsl * 32 + lane) * 4);
        }
#pragma unroll
        for (int ks = 0; ks < 2; ks++) {
#pragma unroll
            for (int mi = 0; mi < 4; mi++) {
                int ms = wm * 4 + mi;
                float4 a4h = *reinterpret_cast<const float4*>(sA + ((ms * 2 + ks) * 32 + lane) * 4);
                float4 a4l = *reinterpret_cast<const float4*>(sA + 2048 + ((ms * 2 + ks) * 32 + lane) * 4);
                uint32_t ah[4] = {__float_as_uint(a4h.x), __float_as_uint(a4h.y),
                                  __float_as_uint(a4h.z), __float_as_uint(a4h.w)};
                uint32_t al[4] = {__float_as_uint(a4l.x), __float_as_uint(a4l.y),
                                  __float_as_uint(a4l.z), __float_as_uint(a4l.w)};
#pragma unroll
                for (int ni = 0; ni < 2; ni++) {
                    float* a4 = &acc[(mi * 2 + ni) * 4];
                    uint32_t bhk0 = (ks == 0) ? __float_as_uint(bh[ni].x) : __float_as_uint(bh[ni].z);
                    uint32_t bhk1 = (ks == 0) ? __float_as_uint(bh[ni].y) : __float_as_uint(bh[ni].w);
                    uint32_t blk0 = (ks == 0) ? __float_as_uint(bl[ni].x) : __float_as_uint(bl[ni].z);
                    uint32_t blk1 = (ks == 0) ? __float_as_uint(bl[ni].y) : __float_as_uint(bl[ni].w);
                    mma8(a4, al, bhk0, bhk1);
                    mma8(a4, ah, blk0, blk1);
                    mma8(a4, ah, bhk0, bhk1);
                }
            }
        }
    };

    auto fold = [&]() {
#pragma unroll
        for (int i = 0; i < 32; i++) { mst[i] = __fadd_rn(mst[i], acc[i]); acc[i] = 0.f; }
    };

    const int NG = (KT + 1) >> 1;
    issueG(0); cp_commit();
    issueG(1); cp_commit();

    for (int g = 0; g < NG; g++) {
        cp_wait<1>();
        __syncthreads();
        int kt = g * 2;
        compute(kt % STAGES_T);
        if (((kt + 1) & 3) == 0 || kt == KT - 1) fold();
        if (kt + 1 < KT) {
            compute((kt + 1) % STAGES_T);
            if (((kt + 2) & 3) == 0 || kt + 1 == KT - 1) fold();
        }
        __syncthreads();
        issueG(g + 2);
        cp_commit();
    }

    float* Cb = C + (long long)b * M * 256;
#pragma unroll
    for (int mi = 0; mi < 4; mi++) {
#pragma unroll
        for (int ni = 0; ni < 2; ni++) {
            int rB = mt * 128 + wm * 64 + mi * 16 + gid;
            int cB = nt4 * 64 + wn * 16 + ni * 8 + tig * 2;
#pragma unroll
            for (int rr = 0; rr < 2; rr++) {
                int r = rB + rr * 8;
                if (r < M) {
#pragma unroll
                    for (int c2 = 0; c2 < 2; c2++) {
                        int c = cB + c2;
                        float v = mst[(mi * 2 + ni) * 4 + rr * 2 + c2];
                        Cb[(size_t)r * 256 + c] = v;
                        // dual store: cat4 A-image feature tile (fw: ktOff=0, bw: ktOff=16)
                        int gm = b * NN + r;
                        float h, l;
                        split2(v, h, l);
                        int off = a_frag_off(gm & 127, c & 15);
                        long long base = ((long long)(gm >> 7) * KTF + ktOff + (c >> 4)) * 4096;
                        img[base + off] = h;
                        img[base + 2048 + off] = l;
                    }
                }
            }
        }
    }
}

// ---------------- fused weight transpose ----------------
__global__ void k_transW(const float* __restrict__ Wf, const float* __restrict__ Wz,
                         const float* __restrict__ Wr, const float* __restrict__ Wt,
                         float* __restrict__ WfT, float* __restrict__ WzT,
                         float* __restrict__ WrT, float* __restrict__ WtT)
{
    __shared__ float t[32][33];
    int x = threadIdx.x, y = threadIdx.y;
    const float* srcs[4] = {Wf, Wz, Wr, Wt};
    float* dsts[4] = {WfT, WzT, WrT, WtT};
    const int Cs[4] = {1024, 512, 512, 512};
#pragma unroll
    for (int w = 0; w < 4; w++) {
        int C = Cs[w];
        const int R = 256;
        if (blockIdx.x * 32 >= C) continue;
        int bx = blockIdx.x * 32, by = blockIdx.y * 32;
        __syncthreads();
#pragma unroll
        for (int j = 0; j < 32; j += 8) {
            int r = by + y + j, c = bx + x;
            t[y + j][x] = srcs[w][(size_t)r * C + c];
        }
        __syncthreads();
#pragma unroll
        for (int j = 0; j < 32; j += 8) {
            int r = bx + y + j, c = by + x;
            dsts[w][(size_t)r * R + c] = t[x][y + j];
        }
    }
}

// ---------------- host side ----------------
template<int MODE, int FOLD>
static void run_frag(const float* pA, const float* pB, float* C, int M, int MT, int KT, int KTD,
                     int batch, const float* bias, const float* a1, const float* a2,
                     float* img, int imgOn)
{
    cudaFuncSetAttribute(gemm_frag<MODE, FOLD>, cudaFuncAttributeMaxDynamicSharedMemorySize, FRAG_SMEM);
    dim3 grid(4, MT, batch);
    gemm_frag<MODE, FOLD><<<grid, 256, FRAG_SMEM>>>(pA, pB, C, M, MT, KT, KTD, bias, a1, a2, img, imgOn);
}

static void run_store(const float* pA, const float* pB, float* C, int M, int MT, int KT,
                      float* img, int ktOff)
{
    cudaFuncSetAttribute(gemm_frag_store, cudaFuncAttributeMaxDynamicSharedMemorySize, FRAG_SMEM);
    dim3 grid(4, MT, BB);
    gemm_frag_store<<<grid, 256, FRAG_SMEM>>>(pA, pB, C, M, MT, KT, img, ktOff);
}

extern "C" void kernel_launch(void* const* d_in, const int* in_sizes, int n_in,
                              void* d_out, int out_size)
{
    const float* node_feature = (const float*)d_in[0];
    const float* node2edge    = (const float*)d_in[1];
    const float* edge2node    = (const float*)d_in[2];
    const float* Wz = (const float*)d_in[3];
    const float* Wr = (const float*)d_in[4];
    const float* Wt = (const float*)d_in[5];
    const float* Wf = (const float*)d_in[6];
    const float* bf = (const float*)d_in[7];
    float* out = (float*)d_out;

    float *pA1, *pA2, *pA3, *pA4, *pBnf, *pBt1, *pBt2, *pAct, *pAct2, *pWf, *pWz, *pWr, *pWt;
    float *bwP, *fwP, *zg, *rg, *nf1;
    float *WfT, *WzT, *WrT, *WtT;
    cudaGetSymbolAddress((void**)&pA1, g_pA1);
    cudaGetSymbolAddress((void**)&pA2, g_pA2);
    cudaGetSymbolAddress((void**)&pA3, g_pA3);
    cudaGetSymbolAddress((void**)&pA4, g_pA4);
    cudaGetSymbolAddress((void**)&pBnf, g_pBnf);
    cudaGetSymbolAddress((void**)&pBt1, g_pBt1);
    cudaGetSymbolAddress((void**)&pBt2, g_pBt2);
    cudaGetSymbolAddress((void**)&pAct, g_pAct);
    cudaGetSymbolAddress((void**)&pAct2, g_pAct2);
    cudaGetSymbolAddress((void**)&pWf, g_pWf);
    cudaGetSymbolAddress((void**)&pWz, g_pWz);
    cudaGetSymbolAddress((void**)&pWr, g_pWr);
    cudaGetSymbolAddress((void**)&pWt, g_pWt);
    cudaGetSymbolAddress((void**)&bwP,  g_bw);
    cudaGetSymbolAddress((void**)&fwP,  g_fw);
    cudaGetSymbolAddress((void**)&zg,   g_zg);
    cudaGetSymbolAddress((void**)&rg,   g_rg);
    cudaGetSymbolAddress((void**)&nf1,  g_nf1);
    cudaGetSymbolAddress((void**)&WfT,  g_WfT);
    cudaGetSymbolAddress((void**)&WzT,  g_WzT);
    cudaGetSymbolAddress((void**)&WrT,  g_WrT);
    cudaGetSymbolAddress((void**)&WtT,  g_WtT);

    // weights: one fused transpose launch, then B-images
    k_transW<<<dim3(32, 8), dim3(32, 8)>>>(Wf, Wz, Wr, Wt, WfT, WzT, WrT, WtT);
    k_packB<<<dim3(KTF, 2, 1), 256>>>(WfT, pWf, 4 * HH, KTF);
    k_packB<<<dim3(KTG, 2, 1), 256>>>(WzT, pWz, 2 * HH, KTG);
    k_packB<<<dim3(KTG, 2, 1), 256>>>(WrT, pWr, 2 * HH, KTG);
    k_packB<<<dim3(KTG, 2, 1), 256>>>(WtT, pWt, 2 * HH, KTG);

    const long long sPQ = (long long)EE * NN;
    const int MR = BB * NN;   // 8000

    // pack adjacency fragment images (reused both hops)
    k_packA<0><<<dim3(KT12, MT12, BB), 256>>>(node2edge, pA1, EE, NN, NN, sPQ, MT12, KT12);
    k_packA<1><<<dim3(KT12, MT12, BB), 256>>>(edge2node, pA2, EE, NN, EE, sPQ, MT12, KT12);
    k_packA<0><<<dim3(KT34, MT34, BB), 256>>>(edge2node, pA3, NN, EE, EE, sPQ, MT34, KT34);
    k_packA<1><<<dim3(KT34, MT34, BB), 256>>>(node2edge, pA4, NN, EE, NN, sPQ, MT34, KT34);

    const float* nfIn = node_feature;
    for (int hop = 0; hop < 2; hop++) {
        float* nfOut = (hop == 1) ? out : nf1;

        // nf B-image: hop 0 packs from input; hop 1 already written by hop-0 GRU epilogue
        if (hop == 0)
            k_packB<<<dim3(KT12, 2, BB), 256>>>(nfIn, pBnf, NN, KT12);

        // tmp1/tmp2 GEMMs write directly as B-fragment images (MODE 4)
        run_frag<4, 4>(pA1, pBnf, pBt1, EE, MT12, KT12, KT34, BB, nullptr, nullptr, nullptr, nullptr, 0);
        run_frag<4, 4>(pA2, pBnf, pBt2, EE, MT12, KT12, KT34, BB, nullptr, nullptr, nullptr, nullptr, 0);

        // bw/fw: row-major + cat4 A-image feature tiles (fw -> 0-15, bw -> 16-31)
        run_store(pA4, pBt2, fwP, NN, MT34, KT34, pAct, 0);
        run_store(pA3, pBt1, bwP, NN, MT34, KT34, pAct, 16);

        // cat4 product features (tiles 32-63)
        k_packA_f<0><<<dim3(32, MTS), 256>>>(fwP, bwP, pAct, KTF, 32);

        // fusion GEMM: writes agg DIRECTLY as A-image tiles 16-31 of pAct2
        run_frag<2, 1>(pAct, pWf, nullptr, MR, MTS, KTF, 0, 1, bf, fwP, bwP, pAct2, 0);

        // GRU step: nf half (tiles 0-15) of pAct2
        k_packA_f<1><<<dim3(16, MTS), 256>>>(nfIn, nullptr, pAct2, KTG, 0);
        run_frag<1, 1>(pAct2, pWz, zg, MR, MTS, KTG, 0, 1, nullptr, nullptr, nullptr, nullptr, 0);
        run_frag<1, 1>(pAct2, pWr, rg, MR, MTS, KTG, 0, 1, nullptr, nullptr, nullptr, nullptr, 0);
        k_packA_f<2><<<dim3(16, MTS), 256>>>(rg, nfIn, pAct2, KTG, 0);
        // GRU out: row-major nfOut; hop 0 also writes next hop's nf B-image
        run_frag<3, 1>(pAct2, pWt, nfOut, MR, MTS, KTG, KT12, 1, nullptr, zg, nfIn, pBnf, hop == 0 ? 1 : 0);

        nfIn = nfOut;
    }
}